// round 1
// baseline (speedup 1.0000x reference)
#include <cuda_runtime.h>
#include <cuda_bf16.h>
#include <math.h>
#include <stdint.h>

// ---------------- problem constants ----------------
#define BB   16
#define SS   1024
#define DIN  768
#define EE   512
#define HH   8
#define LL   2
#define FF   2048
#define DH   64
#define MTOK (BB*SS)          // 16384 rows

// ---------------- scratch (static device allocations are the sanctioned path) ----------------
__device__ float g_x  [MTOK*EE];        // residual stream
__device__ float g_a  [MTOK*EE];        // LN output
__device__ float g_qkv[MTOK*3*EE];      // qkv
__device__ float g_sc [(size_t)BB*HH*SS*SS]; // attention scores (537 MB)
__device__ float g_o  [MTOK*EE];        // attention output
__device__ float g_f  [MTOK*FF];        // ffn hidden
__device__ float g_xp [MTOK*EE];        // precomputed x-part of recurrence
__device__ float g_h  [BB*EE];          // final hidden state

// ---------------- helpers ----------------
__device__ __forceinline__ float gelu_exact(float x) {
    return 0.5f * x * (1.0f + erff(x * 0.7071067811865476f));
}

// =====================================================================
// Generic SGEMM: C[M,N] = epilogue( A[M,K] * B^T + bias )
//   A row-major lda; B: if !BT -> B[n,k] at B[n*ldb+k] (weight layout)
//                       if  BT -> B[n,k] at B[k*ldb+n] (K-major, for A*V)
//   EPI: 0 = bias, 1 = bias+gelu, 2 = C += acc + bias (residual)
//   Batched over blockIdx.z with z = b*Hdim + h, per-b / per-h strides.
//   Requires: M % 128 == 0, K % 8 == 0, N % 4 == 0, lda/ldb/ldc % 4 == 0.
// =====================================================================
template<int EPI, bool BT>
__global__ __launch_bounds__(256, 2)
void gemm_kernel(const float* __restrict__ A, const float* __restrict__ B,
                 const float* __restrict__ bias, float* __restrict__ C,
                 int M, int N, int K, int lda, int ldb, int ldc, int Hdim,
                 long long sAb, long long sAh, long long sBb, long long sBh,
                 long long sCb, long long sCh)
{
    {
        int z = blockIdx.z;
        int bb = z / Hdim, hh = z % Hdim;
        A += bb * sAb + hh * sAh;
        B += bb * sBb + hh * sBh;
        C += bb * sCb + hh * sCh;
    }
    __shared__ float As[8][128];
    __shared__ float Bs[8][128];

    const int tid = threadIdx.x;
    const int bm = blockIdx.y * 128;
    const int bn = blockIdx.x * 128;
    const int ty = tid >> 4;        // 0..15
    const int tx = tid & 15;        // 0..15

    const int am = tid >> 1;        // 0..127
    const int ak = (tid & 1) * 4;   // 0 or 4

    float acc[8][8] = {};

    for (int k0 = 0; k0 < K; k0 += 8) {
        // ---- load A tile (128 x 8) ----
        {
            float4 av = *(const float4*)(A + (long long)(bm + am) * lda + k0 + ak);
            As[ak + 0][am] = av.x; As[ak + 1][am] = av.y;
            As[ak + 2][am] = av.z; As[ak + 3][am] = av.w;
        }
        // ---- load B tile (128 x 8) ----
        if constexpr (!BT) {
            int bnr = bn + am;
            float4 bv = {0.f, 0.f, 0.f, 0.f};
            if (bnr < N) bv = *(const float4*)(B + (long long)bnr * ldb + k0 + ak);
            Bs[ak + 0][am] = bv.x; Bs[ak + 1][am] = bv.y;
            Bs[ak + 2][am] = bv.z; Bs[ak + 3][am] = bv.w;
        } else {
            int kk = tid >> 5;             // 0..7
            int nn = (tid & 31) * 4;       // 0..124
            int bc = bn + nn;
            float4 bv = {0.f, 0.f, 0.f, 0.f};
            if (bc < N) bv = *(const float4*)(B + (long long)(k0 + kk) * ldb + bc);
            *(float4*)&Bs[kk][nn] = bv;
        }
        __syncthreads();

        #pragma unroll
        for (int kk = 0; kk < 8; kk++) {
            float a[8], b[8];
            *(float4*)&a[0] = *(const float4*)&As[kk][ty * 8];
            *(float4*)&a[4] = *(const float4*)&As[kk][ty * 8 + 4];
            *(float4*)&b[0] = *(const float4*)&Bs[kk][tx * 8];
            *(float4*)&b[4] = *(const float4*)&Bs[kk][tx * 8 + 4];
            #pragma unroll
            for (int i = 0; i < 8; i++)
                #pragma unroll
                for (int j = 0; j < 8; j++)
                    acc[i][j] += a[i] * b[j];
        }
        __syncthreads();
    }

    // ---- epilogue ----
    const int crow = bm + ty * 8;
    const int ccol = bn + tx * 8;
    #pragma unroll
    for (int i = 0; i < 8; i++) {
        long long ro = (long long)(crow + i) * ldc;
        #pragma unroll
        for (int jj = 0; jj < 8; jj += 4) {
            int col = ccol + jj;
            if (col >= N) continue;
            float4 v;
            v.x = acc[i][jj + 0]; v.y = acc[i][jj + 1];
            v.z = acc[i][jj + 2]; v.w = acc[i][jj + 3];
            if (bias) {
                v.x += bias[col + 0]; v.y += bias[col + 1];
                v.z += bias[col + 2]; v.w += bias[col + 3];
            }
            if (EPI == 1) {
                v.x = gelu_exact(v.x); v.y = gelu_exact(v.y);
                v.z = gelu_exact(v.z); v.w = gelu_exact(v.w);
            }
            if (EPI == 2) {
                float4 old = *(const float4*)(C + ro + col);
                v.x += old.x; v.y += old.y; v.z += old.z; v.w += old.w;
            }
            *(float4*)(C + ro + col) = v;
        }
    }
}

// =====================================================================
// LayerNorm over last dim (512). One CTA (128 threads) per row.
// =====================================================================
__global__ void ln_kernel(const float* __restrict__ x, const float* __restrict__ g,
                          const float* __restrict__ b, float* __restrict__ y)
{
    long long row = blockIdx.x;
    const float* xr = x + row * EE;
    int tid = threadIdx.x;
    float4 v = *(const float4*)(xr + tid * 4);
    float s  = v.x + v.y + v.z + v.w;
    float s2 = v.x * v.x + v.y * v.y + v.z * v.z + v.w * v.w;
    #pragma unroll
    for (int o = 16; o > 0; o >>= 1) {
        s  += __shfl_xor_sync(0xffffffffu, s, o);
        s2 += __shfl_xor_sync(0xffffffffu, s2, o);
    }
    __shared__ float ss[4], ssq[4];
    int w = tid >> 5, l = tid & 31;
    if (l == 0) { ss[w] = s; ssq[w] = s2; }
    __syncthreads();
    s  = ss[0] + ss[1] + ss[2] + ss[3];
    s2 = ssq[0] + ssq[1] + ssq[2] + ssq[3];
    float m   = s * (1.0f / EE);
    float var = s2 * (1.0f / EE) - m * m;
    float inv = rsqrtf(var + 1e-5f);
    float4 gg = *(const float4*)(g + tid * 4);
    float4 bb = *(const float4*)(b + tid * 4);
    float4 o4;
    o4.x = (v.x - m) * inv * gg.x + bb.x;
    o4.y = (v.y - m) * inv * gg.y + bb.y;
    o4.z = (v.z - m) * inv * gg.z + bb.z;
    o4.w = (v.w - m) * inv * gg.w + bb.w;
    *(float4*)(y + row * EE + tid * 4) = o4;
}

// =====================================================================
// Softmax over rows of length 1024, scale applied first. 256 threads/row.
// =====================================================================
__global__ void softmax_kernel(float* __restrict__ s)
{
    long long row = blockIdx.x;
    float* p = s + row * (long long)SS;
    int tid = threadIdx.x;
    float4 v = *(float4*)(p + tid * 4);
    const float sc = 0.125f; // 1/sqrt(64)
    v.x *= sc; v.y *= sc; v.z *= sc; v.w *= sc;
    float mx = fmaxf(fmaxf(v.x, v.y), fmaxf(v.z, v.w));
    #pragma unroll
    for (int o = 16; o > 0; o >>= 1) mx = fmaxf(mx, __shfl_xor_sync(0xffffffffu, mx, o));
    __shared__ float wm[8], wsum[8];
    int w = tid >> 5, l = tid & 31;
    if (l == 0) wm[w] = mx;
    __syncthreads();
    mx = fmaxf(fmaxf(fmaxf(wm[0], wm[1]), fmaxf(wm[2], wm[3])),
               fmaxf(fmaxf(wm[4], wm[5]), fmaxf(wm[6], wm[7])));
    v.x = expf(v.x - mx); v.y = expf(v.y - mx);
    v.z = expf(v.z - mx); v.w = expf(v.w - mx);
    float sum = v.x + v.y + v.z + v.w;
    #pragma unroll
    for (int o = 16; o > 0; o >>= 1) sum += __shfl_xor_sync(0xffffffffu, sum, o);
    if (l == 0) wsum[w] = sum;
    __syncthreads();
    sum = wsum[0] + wsum[1] + wsum[2] + wsum[3] + wsum[4] + wsum[5] + wsum[6] + wsum[7];
    float r = 1.0f / sum;
    v.x *= r; v.y *= r; v.z *= r; v.w *= r;
    *(float4*)(p + tid * 4) = v;
}

// =====================================================================
// Mamba-style recurrence. 16 batches x cluster-of-8 CTAs (128 CTAs resident).
// Each CTA owns 64 output features; its 64x512 weight slice lives in REGISTERS
// (128 regs/thread). h[512] double-buffered in SMEM; new chunks broadcast to
// all 8 peers via mapa + st.shared::cluster; one cluster barrier per step.
// =====================================================================
__global__ void __cluster_dims__(8, 1, 1) __launch_bounds__(256, 1)
recur_kernel(const float* __restrict__ XP, const float* __restrict__ h0,
             const float* __restrict__ Wi2h, float* __restrict__ hout)
{
    __shared__ float hbuf[2 * EE];     // double-buffered hidden state
    __shared__ float partial[256];     // 4 k-parts x 64 features

    const int tid = threadIdx.x;
    const int b = blockIdx.x >> 3;
    const int r = blockIdx.x & 7;
    const int part = tid >> 6;         // 0..3 (k-chunk of 128)
    const int e    = tid & 63;         // local output feature

    // weight slice -> registers (one-time, ~33 MB total traffic)
    float4 w[32];
    {
        const float* wsrc = Wi2h + (long long)(r * 64 + e) * (2 * EE) + EE + part * 128;
        #pragma unroll
        for (int i = 0; i < 32; i++) w[i] = *(const float4*)(wsrc + i * 4);
    }
    // init h (every CTA keeps a full copy)
    if (tid < 128) *(float4*)(hbuf + tid * 4) = *(const float4*)(h0 + b * EE + tid * 4);

    uint32_t hb = (uint32_t)__cvta_generic_to_shared(hbuf);
    __syncthreads();
    asm volatile("barrier.cluster.arrive.aligned;" ::: "memory");
    asm volatile("barrier.cluster.wait.aligned;"   ::: "memory");

    const long long xpbase = (long long)b * SS * EE + r * 64 + e;

    for (int t = 0; t < SS; t++) {
        float xpv = 0.f;
        if (tid < 64) xpv = __ldg(XP + xpbase + (long long)t * EE);

        const float* hr = hbuf + (t & 1) * EE + part * 128;
        float acc = 0.f;
        #pragma unroll
        for (int i = 0; i < 32; i++) {
            float4 h4 = *(const float4*)(hr + i * 4);  // broadcast within warp
            acc += w[i].x * h4.x; acc += w[i].y * h4.y;
            acc += w[i].z * h4.z; acc += w[i].w * h4.w;
        }
        partial[part * 64 + e] = acc;
        __syncthreads();

        if (tid < 64) {
            float sm = partial[e] + partial[64 + e] + partial[128 + e] + partial[192 + e] + xpv;
            float hn = tanhf(sm);
            hn = (hn > 0.f) ? hn : 0.f;     // relu(tanh) per reference threshold
            uint32_t loff = hb + (uint32_t)((((t + 1) & 1) * EE + r * 64 + e) * 4);
            #pragma unroll
            for (int c = 0; c < 8; c++) {
                uint32_t ra;
                asm("mapa.shared::cluster.u32 %0, %1, %2;" : "=r"(ra) : "r"(loff), "r"(c));
                asm volatile("st.shared::cluster.f32 [%0], %1;" :: "r"(ra), "f"(hn));
            }
        }
        asm volatile("barrier.cluster.arrive.aligned;" ::: "memory");
        asm volatile("barrier.cluster.wait.aligned;"   ::: "memory");
    }
    // after t=1023 the final state sits in buffer 0
    if (tid < 64) hout[b * EE + r * 64 + e] = hbuf[r * 64 + e];
}

// =====================================================================
// Head: out = h @ Wh2o^T + bh2o ; logits = out @ Wc^T + bc ; sigmoid.
// One CTA (512 threads) per batch element.
// =====================================================================
__global__ void head_kernel(const float* __restrict__ hfin, const float* __restrict__ Wh2o,
                            const float* __restrict__ bh2o, const float* __restrict__ Wc,
                            const float* __restrict__ bc, float* __restrict__ out, int half)
{
    int b = blockIdx.x, tid = threadIdx.x;
    __shared__ float hrow[EE];
    __shared__ float red[EE];
    hrow[tid] = hfin[b * EE + tid];
    __syncthreads();
    const float* wr = Wh2o + (long long)tid * EE;
    float acc = bh2o[tid];
    #pragma unroll 8
    for (int f = 0; f < EE; f += 4) {
        float4 w4 = *(const float4*)(wr + f);
        acc += w4.x * hrow[f] + w4.y * hrow[f + 1] + w4.z * hrow[f + 2] + w4.w * hrow[f + 3];
    }
    red[tid] = acc * Wc[tid];
    __syncthreads();
    for (int s = 256; s > 0; s >>= 1) {
        if (tid < s) red[tid] += red[tid + s];
        __syncthreads();
    }
    if (tid == 0) {
        float lg = red[0] + bc[0];
        out[b] = lg;                             // logits
        out[half + b] = 1.f / (1.f + expf(-lg)); // probas
    }
}

// ---------------- host-side launch helpers ----------------
static void run_gemm(int epi, bool bt,
                     const float* A, const float* B, const float* bias, float* C,
                     int M, int N, int K, int lda, int ldb, int ldc,
                     int Z, int Hdim,
                     long long sAb, long long sAh, long long sBb, long long sBh,
                     long long sCb, long long sCh)
{
    dim3 grid((N + 127) / 128, M / 128, Z);
    dim3 block(256);
    if (bt)
        gemm_kernel<0, true ><<<grid, block>>>(A, B, bias, C, M, N, K, lda, ldb, ldc, Hdim, sAb, sAh, sBb, sBh, sCb, sCh);
    else if (epi == 0)
        gemm_kernel<0, false><<<grid, block>>>(A, B, bias, C, M, N, K, lda, ldb, ldc, Hdim, sAb, sAh, sBb, sBh, sCb, sCh);
    else if (epi == 1)
        gemm_kernel<1, false><<<grid, block>>>(A, B, bias, C, M, N, K, lda, ldb, ldc, Hdim, sAb, sAh, sBb, sBh, sCb, sCh);
    else
        gemm_kernel<2, false><<<grid, block>>>(A, B, bias, C, M, N, K, lda, ldb, ldc, Hdim, sAb, sAh, sBb, sBh, sCb, sCh);
}

extern "C" void kernel_launch(void* const* d_in, const int* in_sizes, int n_in,
                              void* d_out, int out_size)
{
    const float* bm   = (const float*)d_in[0];
    const float* h0   = (const float*)d_in[1];
    const float* Wp   = (const float*)d_in[2];
    const float* bp   = (const float*)d_in[3];
    const float* ln1g = (const float*)d_in[4];
    const float* ln1b = (const float*)d_in[5];
    const float* Wqkv = (const float*)d_in[6];
    const float* bqkv = (const float*)d_in[7];
    const float* Wo   = (const float*)d_in[8];
    const float* bo   = (const float*)d_in[9];
    const float* ln2g = (const float*)d_in[10];
    const float* ln2b = (const float*)d_in[11];
    const float* W1   = (const float*)d_in[12];
    const float* b1   = (const float*)d_in[13];
    const float* W2   = (const float*)d_in[14];
    const float* b2   = (const float*)d_in[15];
    const float* Wi2h = (const float*)d_in[16];
    const float* bi2h = (const float*)d_in[17];
    const float* Wh2o = (const float*)d_in[18];
    const float* bh2o = (const float*)d_in[19];
    const float* Wc   = (const float*)d_in[20];
    const float* bc   = (const float*)d_in[21];
    float* out = (float*)d_out;

    float *px, *pa, *pq, *ps, *po, *pf, *pxp, *ph;
    cudaGetSymbolAddress((void**)&px,  g_x);
    cudaGetSymbolAddress((void**)&pa,  g_a);
    cudaGetSymbolAddress((void**)&pq,  g_qkv);
    cudaGetSymbolAddress((void**)&ps,  g_sc);
    cudaGetSymbolAddress((void**)&po,  g_o);
    cudaGetSymbolAddress((void**)&pf,  g_f);
    cudaGetSymbolAddress((void**)&pxp, g_xp);
    cudaGetSymbolAddress((void**)&ph,  g_h);

    // 1) modality projection: x = bm @ Wp^T + bp
    run_gemm(0, false, bm, Wp, bp, px, MTOK, EE, DIN, DIN, DIN, EE,
             1, 1, 0, 0, 0, 0, 0, 0);

    for (int l = 0; l < LL; l++) {
        const float* wqkv = Wqkv + (size_t)l * 3 * EE * EE;
        const float* bqk  = bqkv + (size_t)l * 3 * EE;
        const float* wo   = Wo   + (size_t)l * EE * EE;
        const float* bo_  = bo   + (size_t)l * EE;
        const float* w1   = W1   + (size_t)l * FF * EE;
        const float* b1_  = b1   + (size_t)l * FF;
        const float* w2   = W2   + (size_t)l * EE * FF;
        const float* b2_  = b2   + (size_t)l * EE;

        // pre-LN attention
        ln_kernel<<<MTOK, 128>>>(px, ln1g + l * EE, ln1b + l * EE, pa);
        run_gemm(0, false, pa, wqkv, bqk, pq, MTOK, 3 * EE, EE, EE, EE, 3 * EE,
                 1, 1, 0, 0, 0, 0, 0, 0);

        // scores[b,h] = Q @ K^T   (batched, z = b*H + h)
        run_gemm(0, false, pq, pq + EE, nullptr, ps,
                 SS, SS, DH, 3 * EE, 3 * EE, SS,
                 BB * HH, HH,
                 (long long)SS * 3 * EE, DH,
                 (long long)SS * 3 * EE, DH,
                 (long long)HH * SS * SS, (long long)SS * SS);

        softmax_kernel<<<BB * HH * SS, 256>>>(ps);

        // O[b,h] = A @ V   (B is K-major -> BT path)
        run_gemm(0, true, ps, pq + 2 * EE, nullptr, po,
                 SS, DH, SS, SS, 3 * EE, EE,
                 BB * HH, HH,
                 (long long)HH * SS * SS, (long long)SS * SS,
                 (long long)SS * 3 * EE, DH,
                 (long long)SS * EE, DH);

        // x += O @ Wo^T + bo
        run_gemm(2, false, po, wo, bo_, px, MTOK, EE, EE, EE, EE, EE,
                 1, 1, 0, 0, 0, 0, 0, 0);

        // pre-LN FFN
        ln_kernel<<<MTOK, 128>>>(px, ln2g + l * EE, ln2b + l * EE, pa);
        run_gemm(1, false, pa, w1, b1_, pf, MTOK, FF, EE, EE, EE, FF,
                 1, 1, 0, 0, 0, 0, 0, 0);
        run_gemm(2, false, pf, w2, b2_, px, MTOK, EE, FF, FF, FF, EE,
                 1, 1, 0, 0, 0, 0, 0, 0);
    }

    // recurrence x-part: xp = x @ Wi2h[:, :E]^T + bi2h   (ldb = 2E)
    run_gemm(0, false, px, Wi2h, bi2h, pxp, MTOK, EE, EE, EE, 2 * EE, EE,
             1, 1, 0, 0, 0, 0, 0, 0);

    // sequential recurrence (persistent, clustered)
    recur_kernel<<<128, 256>>>(pxp, h0, Wi2h, ph);

    // head: logits + sigmoid
    head_kernel<<<BB, 512>>>(ph, Wh2o, bh2o, Wc, bc, out, out_size / 2);
}

// round 4
// speedup vs baseline: 2.4047x; 2.4047x over previous
#include <cuda_runtime.h>
#include <cuda_bf16.h>
#include <math.h>
#include <stdint.h>

// ---------------- problem constants ----------------
#define BB   16
#define SS   1024
#define DIN  768
#define EE   512
#define HH   8
#define LL   2
#define FF   2048
#define DH   64
#define MTOK (BB*SS)          // 16384 rows

// ---------------- scratch ----------------
__device__ float g_x  [MTOK*EE];
__device__ float g_a  [MTOK*EE];
__device__ float g_qkv[MTOK*3*EE];
__device__ float g_sc [(size_t)BB*HH*SS*SS];
__device__ float g_o  [MTOK*EE];
__device__ float g_f  [MTOK*FF];
__device__ float g_xp [MTOK*EE];
__device__ float g_h  [BB*EE];

// ---------------- helpers ----------------
__device__ __forceinline__ float gelu_exact(float x) {
    return 0.5f * x * (1.0f + erff(x * 0.7071067811865476f));
}
__device__ __forceinline__ uint32_t swz128(uint32_t off) {
    return off ^ ((off >> 3) & 0x70);
}
__device__ __forceinline__ void cpasync16(uint32_t dst, const void* src) {
    asm volatile("cp.async.cg.shared.global [%0], [%1], 16;" :: "r"(dst), "l"(src));
}
__device__ __forceinline__ void cp_commit() { asm volatile("cp.async.commit_group;"); }
__device__ __forceinline__ void cp_wait1() { asm volatile("cp.async.wait_group 1;"); }
__device__ __forceinline__ void cp_wait0() { asm volatile("cp.async.wait_group 0;"); }
__device__ __forceinline__ uint32_t smem_u32(const void* p) {
    uint32_t a;
    asm("{ .reg .u64 t; cvta.to.shared.u64 t, %1; cvt.u32.u64 %0, t; }" : "=r"(a) : "l"(p));
    return a;
}
__device__ __forceinline__ uint32_t f2tf(float f) {
    uint32_t u;
    asm("cvt.rna.tf32.f32 %0, %1;" : "=r"(u) : "f"(f));
    return u;
}
// read float at logical (row, col) of a swizzled 128B-row tile
__device__ __forceinline__ float lds_swz(const char* base, int row, int col) {
    return *(const float*)(base + row * 128 + ((col * 4) ^ ((row & 7) << 4)));
}
__device__ __forceinline__ void mma_tf32(float* c, const uint32_t* a, const uint32_t* b) {
    asm volatile(
        "mma.sync.aligned.m16n8k8.row.col.f32.tf32.tf32.f32 "
        "{%0,%1,%2,%3}, {%4,%5,%6,%7}, {%8,%9}, {%0,%1,%2,%3};"
        : "+f"(c[0]), "+f"(c[1]), "+f"(c[2]), "+f"(c[3])
        : "r"(a[0]), "r"(a[1]), "r"(a[2]), "r"(a[3]), "r"(b[0]), "r"(b[1]));
}

// =====================================================================
// tf32 warp-MMA GEMM: C[M,N] = epi( A[M,K] * B^T + bias )
//   A row-major [M,K] lda. B: !BT -> [N,K] ldb (weights); BT -> [K,N] ldb.
//   CTA tile 128 x NT, 256 threads (4 m-warps x 2 n-warps), K chunk 32.
//   EPI: 0=bias, 1=bias+gelu, 2=C += acc + bias
//   Batched via blockIdx.z (z = b*Hdim + h). M%128==0, N%NT==0, K%32==0.
// =====================================================================
template<int EPI, bool BT, int NT>
__global__ void __launch_bounds__(256, 2)
gemm_mma(const float* __restrict__ A, const float* __restrict__ B,
         const float* __restrict__ bias, float* __restrict__ C,
         int M, int N, int K, int lda, int ldb, int ldc, int Hdim,
         long long sAb, long long sAh, long long sBb, long long sBh,
         long long sCb, long long sCh)
{
    {
        int z = blockIdx.z;
        int bb = z / Hdim, hh = z % Hdim;
        A += bb * sAb + hh * sAh;
        B += bb * sBb + hh * sBh;
        C += bb * sCb + hh * sCh;
    }
    extern __shared__ char smem[];
    constexpr int ASZ = 128 * 32 * 4;   // 16 KB per stage
    constexpr int BSZ = NT * 32 * 4;
    constexpr int NW  = NT / 16;        // n-atoms per warp (warp covers NT/2 cols)
    const uint32_t sb = smem_u32(smem);

    const int tid = threadIdx.x;
    const int wid = tid >> 5;
    const int lane = tid & 31;
    const int g  = lane >> 2;           // 0..7
    const int tg = lane & 3;            // 0..3
    const int wm = wid & 3;             // m-warp 0..3
    const int wn = wid >> 2;            // n-warp 0..1
    const int bm = blockIdx.y * 128;
    const int bn = blockIdx.x * NT;

    const int NC = K >> 5;

    float acc[2][NW][4];
    #pragma unroll
    for (int i = 0; i < 2; i++)
        #pragma unroll
        for (int j = 0; j < NW; j++)
            #pragma unroll
            for (int q = 0; q < 4; q++) acc[i][j][q] = 0.f;

    // ---------- tile loaders ----------
    auto loadA = [&](int stage, int k0) {
        uint32_t base = sb + stage * ASZ;
        const float* src0 = A + (long long)bm * lda + k0;
        #pragma unroll
        for (int i = 0; i < 4; i++) {
            int j = tid + i * 256;
            int row = j >> 3;
            int c4  = (j & 7) * 4;
            cpasync16(base + swz128(row * 128 + c4 * 4),
                      src0 + (long long)row * lda + c4);
        }
    };
    auto loadB = [&](int stage, int k0) {
        uint32_t base = sb + 2 * ASZ + stage * BSZ;
        if constexpr (!BT) {
            const float* src0 = B + (long long)bn * ldb + k0;
            #pragma unroll
            for (int i = 0; i < NT / 32; i++) {
                int j = tid + i * 256;
                int row = j >> 3;
                int c4  = (j & 7) * 4;
                cpasync16(base + swz128(row * 128 + c4 * 4),
                          src0 + (long long)row * ldb + c4);
            }
        } else {
            // B is [K,N] (ld=ldb); transpose 32 x NT block into [n][k] layout.
            // Need 32*NT/4 float4 transfers = 8*NT; 256 threads -> NT/32 iters.
            char* bp = smem + 2 * ASZ + stage * BSZ;
            #pragma unroll
            for (int i = 0; i < NT / 32; i++) {
                int j = tid + i * 256;
                int k, n;
                if constexpr (NT == 128) { k = j >> 5; n = (j & 31) * 4; }
                else                     { k = j >> 4; n = (j & 15) * 4; }
                float4 v = *(const float4*)(B + (long long)(k0 + k) * ldb + bn + n);
                *(float*)(bp + swz128((n + 0) * 128 + k * 4)) = v.x;
                *(float*)(bp + swz128((n + 1) * 128 + k * 4)) = v.y;
                *(float*)(bp + swz128((n + 2) * 128 + k * 4)) = v.z;
                *(float*)(bp + swz128((n + 3) * 128 + k * 4)) = v.w;
            }
        }
    };

    auto compute = [&](int stage) {
        const char* Ab = smem + stage * ASZ;
        const char* Bb = smem + 2 * ASZ + stage * BSZ;
        #pragma unroll
        for (int kk = 0; kk < 4; kk++) {
            const int k0 = kk * 8;
            uint32_t afr[2][4];
            #pragma unroll
            for (int ma = 0; ma < 2; ma++) {
                int r0 = wm * 32 + ma * 16 + g;
                afr[ma][0] = f2tf(lds_swz(Ab, r0,     k0 + tg));
                afr[ma][1] = f2tf(lds_swz(Ab, r0 + 8, k0 + tg));
                afr[ma][2] = f2tf(lds_swz(Ab, r0,     k0 + tg + 4));
                afr[ma][3] = f2tf(lds_swz(Ab, r0 + 8, k0 + tg + 4));
            }
            uint32_t bfr[NW][2];
            #pragma unroll
            for (int na = 0; na < NW; na++) {
                int rn = wn * (NT / 2) + na * 8 + g;
                bfr[na][0] = f2tf(lds_swz(Bb, rn, k0 + tg));
                bfr[na][1] = f2tf(lds_swz(Bb, rn, k0 + tg + 4));
            }
            #pragma unroll
            for (int ma = 0; ma < 2; ma++)
                #pragma unroll
                for (int na = 0; na < NW; na++)
                    mma_tf32(acc[ma][na], afr[ma], bfr[na]);
        }
    };

    // ---------- pipelined mainloop ----------
    loadA(0, 0); loadB(0, 0); cp_commit();
    for (int c = 0; c < NC; c++) {
        bool more = (c + 1 < NC);
        if (more) { loadA((c + 1) & 1, (c + 1) << 5); loadB((c + 1) & 1, (c + 1) << 5); cp_commit(); }
        if (more) cp_wait1(); else cp_wait0();
        __syncthreads();
        compute(c & 1);
        __syncthreads();
    }

    // ---------- epilogue ----------
    #pragma unroll
    for (int ma = 0; ma < 2; ma++) {
        int row0 = bm + wm * 32 + ma * 16 + g;
        #pragma unroll
        for (int na = 0; na < NW; na++) {
            int col = bn + wn * (NT / 2) + na * 8 + tg * 2;
            #pragma unroll
            for (int half = 0; half < 2; half++) {
                int row = row0 + half * 8;
                float2 v;
                v.x = acc[ma][na][half * 2 + 0];
                v.y = acc[ma][na][half * 2 + 1];
                if (bias) { v.x += bias[col]; v.y += bias[col + 1]; }
                if (EPI == 1) { v.x = gelu_exact(v.x); v.y = gelu_exact(v.y); }
                long long ro = (long long)row * ldc + col;
                if (EPI == 2) {
                    float2 old = *(const float2*)(C + ro);
                    v.x += old.x; v.y += old.y;
                }
                *(float2*)(C + ro) = v;
            }
        }
    }
}

// =====================================================================
// LayerNorm over last dim (512). One CTA (128 threads) per row.
// =====================================================================
__global__ void ln_kernel(const float* __restrict__ x, const float* __restrict__ g,
                          const float* __restrict__ b, float* __restrict__ y)
{
    long long row = blockIdx.x;
    const float* xr = x + row * EE;
    int tid = threadIdx.x;
    float4 v = *(const float4*)(xr + tid * 4);
    float s  = v.x + v.y + v.z + v.w;
    float s2 = v.x * v.x + v.y * v.y + v.z * v.z + v.w * v.w;
    #pragma unroll
    for (int o = 16; o > 0; o >>= 1) {
        s  += __shfl_xor_sync(0xffffffffu, s, o);
        s2 += __shfl_xor_sync(0xffffffffu, s2, o);
    }
    __shared__ float ss[4], ssq[4];
    int w = tid >> 5, l = tid & 31;
    if (l == 0) { ss[w] = s; ssq[w] = s2; }
    __syncthreads();
    s  = ss[0] + ss[1] + ss[2] + ss[3];
    s2 = ssq[0] + ssq[1] + ssq[2] + ssq[3];
    float m   = s * (1.0f / EE);
    float var = s2 * (1.0f / EE) - m * m;
    float inv = rsqrtf(var + 1e-5f);
    float4 gg = *(const float4*)(g + tid * 4);
    float4 bb = *(const float4*)(b + tid * 4);
    float4 o4;
    o4.x = (v.x - m) * inv * gg.x + bb.x;
    o4.y = (v.y - m) * inv * gg.y + bb.y;
    o4.z = (v.z - m) * inv * gg.z + bb.z;
    o4.w = (v.w - m) * inv * gg.w + bb.w;
    *(float4*)(y + row * EE + tid * 4) = o4;
}

// =====================================================================
// Softmax over rows of length 1024, scale applied first. 256 threads/row.
// =====================================================================
__global__ void softmax_kernel(float* __restrict__ s)
{
    long long row = blockIdx.x;
    float* p = s + row * (long long)SS;
    int tid = threadIdx.x;
    float4 v = *(float4*)(p + tid * 4);
    const float sc = 0.125f;
    v.x *= sc; v.y *= sc; v.z *= sc; v.w *= sc;
    float mx = fmaxf(fmaxf(v.x, v.y), fmaxf(v.z, v.w));
    #pragma unroll
    for (int o = 16; o > 0; o >>= 1) mx = fmaxf(mx, __shfl_xor_sync(0xffffffffu, mx, o));
    __shared__ float wm[8], wsum[8];
    int w = tid >> 5, l = tid & 31;
    if (l == 0) wm[w] = mx;
    __syncthreads();
    mx = fmaxf(fmaxf(fmaxf(wm[0], wm[1]), fmaxf(wm[2], wm[3])),
               fmaxf(fmaxf(wm[4], wm[5]), fmaxf(wm[6], wm[7])));
    v.x = expf(v.x - mx); v.y = expf(v.y - mx);
    v.z = expf(v.z - mx); v.w = expf(v.w - mx);
    float sum = v.x + v.y + v.z + v.w;
    #pragma unroll
    for (int o = 16; o > 0; o >>= 1) sum += __shfl_xor_sync(0xffffffffu, sum, o);
    if (l == 0) wsum[w] = sum;
    __syncthreads();
    sum = wsum[0] + wsum[1] + wsum[2] + wsum[3] + wsum[4] + wsum[5] + wsum[6] + wsum[7];
    float r = 1.0f / sum;
    v.x *= r; v.y *= r; v.z *= r; v.w *= r;
    *(float4*)(p + tid * 4) = v;
}

// =====================================================================
// Mamba-style recurrence (unchanged — passed in R1).
// =====================================================================
__global__ void __cluster_dims__(8, 1, 1) __launch_bounds__(256, 1)
recur_kernel(const float* __restrict__ XP, const float* __restrict__ h0,
             const float* __restrict__ Wi2h, float* __restrict__ hout)
{
    __shared__ float hbuf[2 * EE];
    __shared__ float partial[256];

    const int tid = threadIdx.x;
    const int b = blockIdx.x >> 3;
    const int r = blockIdx.x & 7;
    const int part = tid >> 6;
    const int e    = tid & 63;

    float4 w[32];
    {
        const float* wsrc = Wi2h + (long long)(r * 64 + e) * (2 * EE) + EE + part * 128;
        #pragma unroll
        for (int i = 0; i < 32; i++) w[i] = *(const float4*)(wsrc + i * 4);
    }
    if (tid < 128) *(float4*)(hbuf + tid * 4) = *(const float4*)(h0 + b * EE + tid * 4);

    uint32_t hb = (uint32_t)__cvta_generic_to_shared(hbuf);
    __syncthreads();
    asm volatile("barrier.cluster.arrive.aligned;" ::: "memory");
    asm volatile("barrier.cluster.wait.aligned;"   ::: "memory");

    const long long xpbase = (long long)b * SS * EE + r * 64 + e;

    for (int t = 0; t < SS; t++) {
        float xpv = 0.f;
        if (tid < 64) xpv = __ldg(XP + xpbase + (long long)t * EE);

        const float* hr = hbuf + (t & 1) * EE + part * 128;
        float acc = 0.f;
        #pragma unroll
        for (int i = 0; i < 32; i++) {
            float4 h4 = *(const float4*)(hr + i * 4);
            acc += w[i].x * h4.x; acc += w[i].y * h4.y;
            acc += w[i].z * h4.z; acc += w[i].w * h4.w;
        }
        partial[part * 64 + e] = acc;
        __syncthreads();

        if (tid < 64) {
            float sm = partial[e] + partial[64 + e] + partial[128 + e] + partial[192 + e] + xpv;
            float hn = tanhf(sm);
            hn = (hn > 0.f) ? hn : 0.f;
            uint32_t loff = hb + (uint32_t)((((t + 1) & 1) * EE + r * 64 + e) * 4);
            #pragma unroll
            for (int c = 0; c < 8; c++) {
                uint32_t ra;
                asm("mapa.shared::cluster.u32 %0, %1, %2;" : "=r"(ra) : "r"(loff), "r"(c));
                asm volatile("st.shared::cluster.f32 [%0], %1;" :: "r"(ra), "f"(hn));
            }
        }
        asm volatile("barrier.cluster.arrive.aligned;" ::: "memory");
        asm volatile("barrier.cluster.wait.aligned;"   ::: "memory");
    }
    if (tid < 64) hout[b * EE + r * 64 + e] = hbuf[r * 64 + e];
}

// =====================================================================
// Head (unchanged).
// =====================================================================
__global__ void head_kernel(const float* __restrict__ hfin, const float* __restrict__ Wh2o,
                            const float* __restrict__ bh2o, const float* __restrict__ Wc,
                            const float* __restrict__ bc, float* __restrict__ out, int half)
{
    int b = blockIdx.x, tid = threadIdx.x;
    __shared__ float hrow[EE];
    __shared__ float red[EE];
    hrow[tid] = hfin[b * EE + tid];
    __syncthreads();
    const float* wr = Wh2o + (long long)tid * EE;
    float acc = bh2o[tid];
    #pragma unroll 8
    for (int f = 0; f < EE; f += 4) {
        float4 w4 = *(const float4*)(wr + f);
        acc += w4.x * hrow[f] + w4.y * hrow[f + 1] + w4.z * hrow[f + 2] + w4.w * hrow[f + 3];
    }
    red[tid] = acc * Wc[tid];
    __syncthreads();
    for (int s = 256; s > 0; s >>= 1) {
        if (tid < s) red[tid] += red[tid + s];
        __syncthreads();
    }
    if (tid == 0) {
        float lg = red[0] + bc[0];
        out[b] = lg;
        out[half + b] = 1.f / (1.f + expf(-lg));
    }
}

// ---------------- host-side launch helpers ----------------
template<int EPI, bool BT, int NT>
static void run_mm(const float* A, const float* B, const float* bias, float* C,
                   int M, int N, int K, int lda, int ldb, int ldc,
                   int Z, int Hdim,
                   long long sAb, long long sAh, long long sBb, long long sBh,
                   long long sCb, long long sCh)
{
    int smemsz = 2 * (128 * 32 * 4) + 2 * (NT * 32 * 4);
    cudaFuncSetAttribute(gemm_mma<EPI, BT, NT>,
                         cudaFuncAttributeMaxDynamicSharedMemorySize, smemsz);
    dim3 grid(N / NT, M / 128, Z);
    gemm_mma<EPI, BT, NT><<<grid, 256, smemsz>>>(A, B, bias, C, M, N, K, lda, ldb, ldc,
                                                 Hdim, sAb, sAh, sBb, sBh, sCb, sCh);
}

extern "C" void kernel_launch(void* const* d_in, const int* in_sizes, int n_in,
                              void* d_out, int out_size)
{
    const float* bm   = (const float*)d_in[0];
    const float* h0   = (const float*)d_in[1];
    const float* Wp   = (const float*)d_in[2];
    const float* bp   = (const float*)d_in[3];
    const float* ln1g = (const float*)d_in[4];
    const float* ln1b = (const float*)d_in[5];
    const float* Wqkv = (const float*)d_in[6];
    const float* bqkv = (const float*)d_in[7];
    const float* Wo   = (const float*)d_in[8];
    const float* bo   = (const float*)d_in[9];
    const float* ln2g = (const float*)d_in[10];
    const float* ln2b = (const float*)d_in[11];
    const float* W1   = (const float*)d_in[12];
    const float* b1   = (const float*)d_in[13];
    const float* W2   = (const float*)d_in[14];
    const float* b2   = (const float*)d_in[15];
    const float* Wi2h = (const float*)d_in[16];
    const float* bi2h = (const float*)d_in[17];
    const float* Wh2o = (const float*)d_in[18];
    const float* bh2o = (const float*)d_in[19];
    const float* Wc   = (const float*)d_in[20];
    const float* bc   = (const float*)d_in[21];
    float* out = (float*)d_out;

    float *px, *pa, *pq, *ps, *po, *pf, *pxp, *ph;
    cudaGetSymbolAddress((void**)&px,  g_x);
    cudaGetSymbolAddress((void**)&pa,  g_a);
    cudaGetSymbolAddress((void**)&pq,  g_qkv);
    cudaGetSymbolAddress((void**)&ps,  g_sc);
    cudaGetSymbolAddress((void**)&po,  g_o);
    cudaGetSymbolAddress((void**)&pf,  g_f);
    cudaGetSymbolAddress((void**)&pxp, g_xp);
    cudaGetSymbolAddress((void**)&ph,  g_h);

    // 1) modality projection: x = bm @ Wp^T + bp
    run_mm<0, false, 128>(bm, Wp, bp, px, MTOK, EE, DIN, DIN, DIN, EE,
                          1, 1, 0, 0, 0, 0, 0, 0);

    for (int l = 0; l < LL; l++) {
        const float* wqkv = Wqkv + (size_t)l * 3 * EE * EE;
        const float* bqk  = bqkv + (size_t)l * 3 * EE;
        const float* wo   = Wo   + (size_t)l * EE * EE;
        const float* bo_  = bo   + (size_t)l * EE;
        const float* w1   = W1   + (size_t)l * FF * EE;
        const float* b1_  = b1   + (size_t)l * FF;
        const float* w2   = W2   + (size_t)l * EE * FF;
        const float* b2_  = b2   + (size_t)l * EE;

        // pre-LN attention
        ln_kernel<<<MTOK, 128>>>(px, ln1g + l * EE, ln1b + l * EE, pa);
        run_mm<0, false, 128>(pa, wqkv, bqk, pq, MTOK, 3 * EE, EE, EE, EE, 3 * EE,
                              1, 1, 0, 0, 0, 0, 0, 0);

        // scores[b,h] = Q @ K^T   (batched, z = b*H + h), K = DH = 64
        run_mm<0, false, 128>(pq, pq + EE, nullptr, ps,
                              SS, SS, DH, 3 * EE, 3 * EE, SS,
                              BB * HH, HH,
                              (long long)SS * 3 * EE, DH,
                              (long long)SS * 3 * EE, DH,
                              (long long)HH * SS * SS, (long long)SS * SS);

        softmax_kernel<<<BB * HH * SS, 256>>>(ps);

        // O[b,h] = A @ V   (B is K-major -> BT path, N=64)
        run_mm<0, true, 64>(ps, pq + 2 * EE, nullptr, po,
                            SS, DH, SS, SS, 3 * EE, EE,
                            BB * HH, HH,
                            (long long)HH * SS * SS, (long long)SS * SS,
                            (long long)SS * 3 * EE, DH,
                            (long long)SS * EE, DH);

        // x += O @ Wo^T + bo
        run_mm<2, false, 128>(po, wo, bo_, px, MTOK, EE, EE, EE, EE, EE,
                              1, 1, 0, 0, 0, 0, 0, 0);

        // pre-LN FFN
        ln_kernel<<<MTOK, 128>>>(px, ln2g + l * EE, ln2b + l * EE, pa);
        run_mm<1, false, 128>(pa, w1, b1_, pf, MTOK, FF, EE, EE, EE, FF,
                              1, 1, 0, 0, 0, 0, 0, 0);
        run_mm<2, false, 128>(pf, w2, b2_, px, MTOK, EE, FF, FF, FF, EE,
                              1, 1, 0, 0, 0, 0, 0, 0);
    }

    // recurrence x-part: xp = x @ Wi2h[:, :E]^T + bi2h   (ldb = 2E)
    run_mm<0, false, 128>(px, Wi2h, bi2h, pxp, MTOK, EE, EE, EE, 2 * EE, EE,
                          1, 1, 0, 0, 0, 0, 0, 0);

    // sequential recurrence (persistent, clustered)
    recur_kernel<<<128, 256>>>(pxp, h0, Wi2h, ph);

    // head: logits + sigmoid
    head_kernel<<<BB, 512>>>(ph, Wh2o, bh2o, Wc, bc, out, out_size / 2);
}

// round 5
// speedup vs baseline: 2.5987x; 1.0807x over previous
#include <cuda_runtime.h>
#include <cuda_bf16.h>
#include <math.h>
#include <stdint.h>

// ---------------- problem constants ----------------
#define BB   16
#define SS   1024
#define DIN  768
#define EE   512
#define HH   8
#define LL   2
#define FF   2048
#define DH   64
#define MTOK (BB*SS)          // 16384 rows

// ---------------- scratch ----------------
__device__ float g_x  [MTOK*EE];
__device__ float g_a  [MTOK*EE];
__device__ float g_qkv[MTOK*3*EE];
__device__ float g_o  [MTOK*EE];
__device__ float g_f  [MTOK*FF];
__device__ float g_xp [MTOK*EE];
__device__ float g_h  [BB*EE];

// ---------------- helpers ----------------
__device__ __forceinline__ float gelu_exact(float x) {
    return 0.5f * x * (1.0f + erff(x * 0.7071067811865476f));
}
__device__ __forceinline__ uint32_t swz128(uint32_t off) {
    return off ^ ((off >> 3) & 0x70);
}
__device__ __forceinline__ void cpasync16(uint32_t dst, const void* src) {
    asm volatile("cp.async.cg.shared.global [%0], [%1], 16;" :: "r"(dst), "l"(src));
}
__device__ __forceinline__ void cp_commit() { asm volatile("cp.async.commit_group;"); }
__device__ __forceinline__ void cp_wait1() { asm volatile("cp.async.wait_group 1;"); }
__device__ __forceinline__ void cp_wait0() { asm volatile("cp.async.wait_group 0;"); }
__device__ __forceinline__ uint32_t smem_u32(const void* p) {
    uint32_t a;
    asm("{ .reg .u64 t; cvta.to.shared.u64 t, %1; cvt.u32.u64 %0, t; }" : "=r"(a) : "l"(p));
    return a;
}
__device__ __forceinline__ uint32_t f2tf(float f) {
    uint32_t u;
    asm("cvt.rna.tf32.f32 %0, %1;" : "=r"(u) : "f"(f));
    return u;
}
__device__ __forceinline__ float lds_swz(const char* base, int row, int col) {
    return *(const float*)(base + row * 128 + ((col * 4) ^ ((row & 7) << 4)));
}
__device__ __forceinline__ void mma_tf32(float* c, const uint32_t* a, const uint32_t* b) {
    asm volatile(
        "mma.sync.aligned.m16n8k8.row.col.f32.tf32.tf32.f32 "
        "{%0,%1,%2,%3}, {%4,%5,%6,%7}, {%8,%9}, {%0,%1,%2,%3};"
        : "+f"(c[0]), "+f"(c[1]), "+f"(c[2]), "+f"(c[3])
        : "r"(a[0]), "r"(a[1]), "r"(a[2]), "r"(a[3]), "r"(b[0]), "r"(b[1]));
}

// =====================================================================
// tf32 warp-MMA GEMM: C[M,N] = epi( A[M,K] * B^T + bias )
//   A row-major [M,K] lda; B [N,K] ldb (weight layout).
//   CTA tile 128x128, 256 threads (4x2 warps), K chunk 32, 3-stage pipe.
//   EPI: 0=bias, 1=bias+gelu, 2=C += acc + bias
// =====================================================================
template<int EPI>
__global__ void __launch_bounds__(256, 2)
gemm_mma(const float* __restrict__ A, const float* __restrict__ B,
         const float* __restrict__ bias, float* __restrict__ C,
         int M, int N, int K, int lda, int ldb, int ldc)
{
    extern __shared__ char smem[];
    constexpr int ASZ = 128 * 32 * 4;   // 16 KB per stage
    constexpr int BSZ = 128 * 32 * 4;
    const uint32_t sb = smem_u32(smem);

    const int tid = threadIdx.x;
    const int wid = tid >> 5;
    const int lane = tid & 31;
    const int g  = lane >> 2;
    const int tg = lane & 3;
    const int wm = wid & 3;
    const int wn = wid >> 2;
    const int bm = blockIdx.y * 128;
    const int bn = blockIdx.x * 128;

    const int NC = K >> 5;

    float acc[2][8][4];
    #pragma unroll
    for (int i = 0; i < 2; i++)
        #pragma unroll
        for (int j = 0; j < 8; j++)
            #pragma unroll
            for (int q = 0; q < 4; q++) acc[i][j][q] = 0.f;

    auto loadA = [&](int stage, int k0) {
        uint32_t base = sb + stage * (ASZ + BSZ);
        const float* src0 = A + (long long)bm * lda + k0;
        #pragma unroll
        for (int i = 0; i < 4; i++) {
            int j = tid + i * 256;
            int row = j >> 3;
            int c4  = (j & 7) * 4;
            cpasync16(base + swz128(row * 128 + c4 * 4),
                      src0 + (long long)row * lda + c4);
        }
    };
    auto loadB = [&](int stage, int k0) {
        uint32_t base = sb + stage * (ASZ + BSZ) + ASZ;
        const float* src0 = B + (long long)bn * ldb + k0;
        #pragma unroll
        for (int i = 0; i < 4; i++) {
            int j = tid + i * 256;
            int row = j >> 3;
            int c4  = (j & 7) * 4;
            cpasync16(base + swz128(row * 128 + c4 * 4),
                      src0 + (long long)row * ldb + c4);
        }
    };

    auto compute = [&](int stage) {
        const char* Ab = smem + stage * (ASZ + BSZ);
        const char* Bb = Ab + ASZ;
        #pragma unroll
        for (int kk = 0; kk < 4; kk++) {
            const int k0 = kk * 8;
            uint32_t afr[2][4];
            #pragma unroll
            for (int ma = 0; ma < 2; ma++) {
                int r0 = wm * 32 + ma * 16 + g;
                afr[ma][0] = f2tf(lds_swz(Ab, r0,     k0 + tg));
                afr[ma][1] = f2tf(lds_swz(Ab, r0 + 8, k0 + tg));
                afr[ma][2] = f2tf(lds_swz(Ab, r0,     k0 + tg + 4));
                afr[ma][3] = f2tf(lds_swz(Ab, r0 + 8, k0 + tg + 4));
            }
            uint32_t bfr[8][2];
            #pragma unroll
            for (int na = 0; na < 8; na++) {
                int rn = wn * 64 + na * 8 + g;
                bfr[na][0] = f2tf(lds_swz(Bb, rn, k0 + tg));
                bfr[na][1] = f2tf(lds_swz(Bb, rn, k0 + tg + 4));
            }
            #pragma unroll
            for (int ma = 0; ma < 2; ma++)
                #pragma unroll
                for (int na = 0; na < 8; na++)
                    mma_tf32(acc[ma][na], afr[ma], bfr[na]);
        }
    };

    // ---------- 3-stage pipelined mainloop ----------
    loadA(0, 0); loadB(0, 0); cp_commit();
    loadA(1, 32); loadB(1, 32); cp_commit();
    for (int c = 0; c < NC; c++) {
        if (c + 1 < NC) cp_wait1(); else cp_wait0();
        __syncthreads();
        if (c + 2 < NC) {
            int s = (c + 2) % 3;
            loadA(s, (c + 2) << 5); loadB(s, (c + 2) << 5); cp_commit();
        }
        compute(c % 3);
    }

    // ---------- epilogue ----------
    #pragma unroll
    for (int ma = 0; ma < 2; ma++) {
        int row0 = bm + wm * 32 + ma * 16 + g;
        #pragma unroll
        for (int na = 0; na < 8; na++) {
            int col = bn + wn * 64 + na * 8 + tg * 2;
            #pragma unroll
            for (int half = 0; half < 2; half++) {
                int row = row0 + half * 8;
                float2 v;
                v.x = acc[ma][na][half * 2 + 0];
                v.y = acc[ma][na][half * 2 + 1];
                if (bias) { v.x += bias[col]; v.y += bias[col + 1]; }
                if (EPI == 1) { v.x = gelu_exact(v.x); v.y = gelu_exact(v.y); }
                long long ro = (long long)row * ldc + col;
                if (EPI == 2) {
                    float2 old = *(const float2*)(C + ro);
                    v.x += old.x; v.y += old.y;
                }
                *(float2*)(C + ro) = v;
            }
        }
    }
}

// =====================================================================
// Fused flash attention (tf32). One CTA per (q-tile of 128, b*H+h).
// 256 threads = 8 warps; warp w owns q rows w*16+{g,g+8}.
// K smem stride 68 fl, V stride 72 fl, P stride 132 fl (conflict-free reads).
// =====================================================================
#define KST 68
#define VST 72
#define PST 132
#define FKSZ (128*KST*4)
#define FVSZ (128*VST*4)
#define FL_SMEM (2*FKSZ + 2*FVSZ + 128*PST*4)

__global__ void __launch_bounds__(256, 1)
flash_kernel(const float* __restrict__ qkv, float* __restrict__ o)
{
    extern __shared__ char fs[];
    const int tid = threadIdx.x;
    const int w = tid >> 5, lane = tid & 31;
    const int g = lane >> 2, tg = lane & 3;
    const int qt = blockIdx.x;            // q tile 0..7
    const int z  = blockIdx.y;            // b*H + h
    const int bb = z >> 3, hh = z & 7;

    char* Ks = fs;
    char* Vs = fs + 2 * FKSZ;
    float* Ps = (float*)(fs + 2 * FKSZ + 2 * FVSZ);
    const uint32_t Ksb = smem_u32(Ks), Vsb = smem_u32(Vs);

    const float* qbase = qkv + (size_t)bb * SS * (3 * EE) + hh * DH;

    // ---- Q fragments in registers, pre-scaled by 1/sqrt(DH) ----
    uint32_t qfr[8][4];
    {
        int r0 = qt * 128 + w * 16 + g;
        const float* q0 = qbase + (size_t)r0 * (3 * EE);
        const float* q1 = q0 + (size_t)8 * (3 * EE);
        #pragma unroll
        for (int kk = 0; kk < 8; kk++) {
            qfr[kk][0] = f2tf(0.125f * q0[kk * 8 + tg]);
            qfr[kk][1] = f2tf(0.125f * q1[kk * 8 + tg]);
            qfr[kk][2] = f2tf(0.125f * q0[kk * 8 + tg + 4]);
            qfr[kk][3] = f2tf(0.125f * q1[kk * 8 + tg + 4]);
        }
    }

    float m0 = -1e30f, m1 = -1e30f, l0 = 0.f, l1 = 0.f;
    float oacc[8][4];
    #pragma unroll
    for (int i = 0; i < 8; i++)
        #pragma unroll
        for (int q = 0; q < 4; q++) oacc[i][q] = 0.f;

    auto loadKV = [&](int st, int j) {
        const float* kg = qbase + EE     + (size_t)(j * 128) * (3 * EE);
        const float* vg = qbase + 2 * EE + (size_t)(j * 128) * (3 * EE);
        #pragma unroll
        for (int i = 0; i < 8; i++) {
            int idx = tid + i * 256;            // 0..2047
            int row = idx >> 4, c4 = (idx & 15) * 4;
            cpasync16(Ksb + st * FKSZ + (row * KST + c4) * 4,
                      kg + (size_t)row * (3 * EE) + c4);
            cpasync16(Vsb + st * FVSZ + (row * VST + c4) * 4,
                      vg + (size_t)row * (3 * EE) + c4);
        }
    };

    loadKV(0, 0); cp_commit();

    const int prow0 = (w * 16 + g) * PST;
    const int prow1 = prow0 + 8 * PST;

    for (int j = 0; j < 8; j++) {
        cp_wait0();
        __syncthreads();                     // KV(j) landed; PV(j-1) done everywhere
        if (j + 1 < 8) { loadKV((j + 1) & 1, j + 1); cp_commit(); }

        // ---- S = Q K^T (sacc[na] covers cols na*8 + {2tg, 2tg+1}) ----
        float sacc[16][4];
        #pragma unroll
        for (int na = 0; na < 16; na++)
            #pragma unroll
            for (int q = 0; q < 4; q++) sacc[na][q] = 0.f;

        const float* Kt = (const float*)(Ks + (j & 1) * FKSZ);
        #pragma unroll
        for (int kk = 0; kk < 8; kk++) {
            #pragma unroll
            for (int na = 0; na < 16; na++) {
                int rn = na * 8 + g;
                uint32_t bfr[2];
                bfr[0] = f2tf(Kt[rn * KST + kk * 8 + tg]);
                bfr[1] = f2tf(Kt[rn * KST + kk * 8 + tg + 4]);
                mma_tf32(sacc[na], qfr[kk], bfr);
            }
        }

        // ---- online softmax ----
        float mx0 = -1e30f, mx1 = -1e30f;
        #pragma unroll
        for (int na = 0; na < 16; na++) {
            mx0 = fmaxf(mx0, fmaxf(sacc[na][0], sacc[na][1]));
            mx1 = fmaxf(mx1, fmaxf(sacc[na][2], sacc[na][3]));
        }
        mx0 = fmaxf(mx0, __shfl_xor_sync(0xffffffffu, mx0, 1));
        mx0 = fmaxf(mx0, __shfl_xor_sync(0xffffffffu, mx0, 2));
        mx1 = fmaxf(mx1, __shfl_xor_sync(0xffffffffu, mx1, 1));
        mx1 = fmaxf(mx1, __shfl_xor_sync(0xffffffffu, mx1, 2));
        float nm0 = fmaxf(m0, mx0), nm1 = fmaxf(m1, mx1);
        float a0 = expf(m0 - nm0), a1 = expf(m1 - nm1);
        float rs0 = 0.f, rs1 = 0.f;
        #pragma unroll
        for (int na = 0; na < 16; na++) {
            float p00 = expf(sacc[na][0] - nm0);
            float p01 = expf(sacc[na][1] - nm0);
            float p10 = expf(sacc[na][2] - nm1);
            float p11 = expf(sacc[na][3] - nm1);
            rs0 += p00 + p01; rs1 += p10 + p11;
            int col = na * 8 + tg * 2;
            *(float2*)(Ps + prow0 + col) = make_float2(p00, p01);
            *(float2*)(Ps + prow1 + col) = make_float2(p10, p11);
        }
        rs0 += __shfl_xor_sync(0xffffffffu, rs0, 1);
        rs0 += __shfl_xor_sync(0xffffffffu, rs0, 2);
        rs1 += __shfl_xor_sync(0xffffffffu, rs1, 1);
        rs1 += __shfl_xor_sync(0xffffffffu, rs1, 2);
        l0 = l0 * a0 + rs0; l1 = l1 * a1 + rs1;
        m0 = nm0; m1 = nm1;
        #pragma unroll
        for (int na2 = 0; na2 < 8; na2++) {
            oacc[na2][0] *= a0; oacc[na2][1] *= a0;
            oacc[na2][2] *= a1; oacc[na2][3] *= a1;
        }
        __syncthreads();                    // all warps' P writes visible

        // ---- O += P V ----
        const float* Vt = (const float*)(Vs + (j & 1) * FVSZ);
        #pragma unroll
        for (int kk = 0; kk < 16; kk++) {
            uint32_t pf[4];
            pf[0] = f2tf(Ps[prow0 + kk * 8 + tg]);
            pf[1] = f2tf(Ps[prow1 + kk * 8 + tg]);
            pf[2] = f2tf(Ps[prow0 + kk * 8 + tg + 4]);
            pf[3] = f2tf(Ps[prow1 + kk * 8 + tg + 4]);
            #pragma unroll
            for (int na2 = 0; na2 < 8; na2++) {
                uint32_t bf[2];
                bf[0] = f2tf(Vt[(kk * 8 + tg) * VST + na2 * 8 + g]);
                bf[1] = f2tf(Vt[(kk * 8 + tg + 4) * VST + na2 * 8 + g]);
                mma_tf32(oacc[na2], pf, bf);
            }
        }
    }

    // ---- epilogue: O / l -> gmem ----
    float inv0 = 1.f / l0, inv1 = 1.f / l1;
    int r0 = qt * 128 + w * 16 + g;
    float* ob0 = o + (size_t)(bb * SS + r0) * EE + hh * DH;
    float* ob1 = ob0 + (size_t)8 * EE;
    #pragma unroll
    for (int na2 = 0; na2 < 8; na2++) {
        int col = na2 * 8 + tg * 2;
        *(float2*)(ob0 + col) = make_float2(oacc[na2][0] * inv0, oacc[na2][1] * inv0);
        *(float2*)(ob1 + col) = make_float2(oacc[na2][2] * inv1, oacc[na2][3] * inv1);
    }
}

// =====================================================================
// LayerNorm over last dim (512). One CTA (128 threads) per row.
// =====================================================================
__global__ void ln_kernel(const float* __restrict__ x, const float* __restrict__ g,
                          const float* __restrict__ b, float* __restrict__ y)
{
    long long row = blockIdx.x;
    const float* xr = x + row * EE;
    int tid = threadIdx.x;
    float4 v = *(const float4*)(xr + tid * 4);
    float s  = v.x + v.y + v.z + v.w;
    float s2 = v.x * v.x + v.y * v.y + v.z * v.z + v.w * v.w;
    #pragma unroll
    for (int o = 16; o > 0; o >>= 1) {
        s  += __shfl_xor_sync(0xffffffffu, s, o);
        s2 += __shfl_xor_sync(0xffffffffu, s2, o);
    }
    __shared__ float ss[4], ssq[4];
    int w = tid >> 5, l = tid & 31;
    if (l == 0) { ss[w] = s; ssq[w] = s2; }
    __syncthreads();
    s  = ss[0] + ss[1] + ss[2] + ss[3];
    s2 = ssq[0] + ssq[1] + ssq[2] + ssq[3];
    float m   = s * (1.0f / EE);
    float var = s2 * (1.0f / EE) - m * m;
    float inv = rsqrtf(var + 1e-5f);
    float4 gg = *(const float4*)(g + tid * 4);
    float4 bb = *(const float4*)(b + tid * 4);
    float4 o4;
    o4.x = (v.x - m) * inv * gg.x + bb.x;
    o4.y = (v.y - m) * inv * gg.y + bb.y;
    o4.z = (v.z - m) * inv * gg.z + bb.z;
    o4.w = (v.w - m) * inv * gg.w + bb.w;
    *(float4*)(y + row * EE + tid * 4) = o4;
}

// =====================================================================
// Mamba-style recurrence (unchanged — passed in R1).
// =====================================================================
__global__ void __cluster_dims__(8, 1, 1) __launch_bounds__(256, 1)
recur_kernel(const float* __restrict__ XP, const float* __restrict__ h0,
             const float* __restrict__ Wi2h, float* __restrict__ hout)
{
    __shared__ float hbuf[2 * EE];
    __shared__ float partial[256];

    const int tid = threadIdx.x;
    const int b = blockIdx.x >> 3;
    const int r = blockIdx.x & 7;
    const int part = tid >> 6;
    const int e    = tid & 63;

    float4 w[32];
    {
        const float* wsrc = Wi2h + (long long)(r * 64 + e) * (2 * EE) + EE + part * 128;
        #pragma unroll
        for (int i = 0; i < 32; i++) w[i] = *(const float4*)(wsrc + i * 4);
    }
    if (tid < 128) *(float4*)(hbuf + tid * 4) = *(const float4*)(h0 + b * EE + tid * 4);

    uint32_t hb = (uint32_t)__cvta_generic_to_shared(hbuf);
    __syncthreads();
    asm volatile("barrier.cluster.arrive.aligned;" ::: "memory");
    asm volatile("barrier.cluster.wait.aligned;"   ::: "memory");

    const long long xpbase = (long long)b * SS * EE + r * 64 + e;

    for (int t = 0; t < SS; t++) {
        float xpv = 0.f;
        if (tid < 64) xpv = __ldg(XP + xpbase + (long long)t * EE);

        const float* hr = hbuf + (t & 1) * EE + part * 128;
        float acc = 0.f;
        #pragma unroll
        for (int i = 0; i < 32; i++) {
            float4 h4 = *(const float4*)(hr + i * 4);
            acc += w[i].x * h4.x; acc += w[i].y * h4.y;
            acc += w[i].z * h4.z; acc += w[i].w * h4.w;
        }
        partial[part * 64 + e] = acc;
        __syncthreads();

        if (tid < 64) {
            float sm = partial[e] + partial[64 + e] + partial[128 + e] + partial[192 + e] + xpv;
            float hn = tanhf(sm);
            hn = (hn > 0.f) ? hn : 0.f;
            uint32_t loff = hb + (uint32_t)((((t + 1) & 1) * EE + r * 64 + e) * 4);
            #pragma unroll
            for (int c = 0; c < 8; c++) {
                uint32_t ra;
                asm("mapa.shared::cluster.u32 %0, %1, %2;" : "=r"(ra) : "r"(loff), "r"(c));
                asm volatile("st.shared::cluster.f32 [%0], %1;" :: "r"(ra), "f"(hn));
            }
        }
        asm volatile("barrier.cluster.arrive.aligned;" ::: "memory");
        asm volatile("barrier.cluster.wait.aligned;"   ::: "memory");
    }
    if (tid < 64) hout[b * EE + r * 64 + e] = hbuf[r * 64 + e];
}

// =====================================================================
// Head (unchanged).
// =====================================================================
__global__ void head_kernel(const float* __restrict__ hfin, const float* __restrict__ Wh2o,
                            const float* __restrict__ bh2o, const float* __restrict__ Wc,
                            const float* __restrict__ bc, float* __restrict__ out, int half)
{
    int b = blockIdx.x, tid = threadIdx.x;
    __shared__ float hrow[EE];
    __shared__ float red[EE];
    hrow[tid] = hfin[b * EE + tid];
    __syncthreads();
    const float* wr = Wh2o + (long long)tid * EE;
    float acc = bh2o[tid];
    #pragma unroll 8
    for (int f = 0; f < EE; f += 4) {
        float4 w4 = *(const float4*)(wr + f);
        acc += w4.x * hrow[f] + w4.y * hrow[f + 1] + w4.z * hrow[f + 2] + w4.w * hrow[f + 3];
    }
    red[tid] = acc * Wc[tid];
    __syncthreads();
    for (int s = 256; s > 0; s >>= 1) {
        if (tid < s) red[tid] += red[tid + s];
        __syncthreads();
    }
    if (tid == 0) {
        float lg = red[0] + bc[0];
        out[b] = lg;
        out[half + b] = 1.f / (1.f + expf(-lg));
    }
}

// ---------------- host-side launch helpers ----------------
static const int GEMM_SMEM = 3 * (128 * 32 * 4 + 128 * 32 * 4);  // 98304

template<int EPI>
static void run_mm(const float* A, const float* B, const float* bias, float* C,
                   int M, int N, int K, int lda, int ldb, int ldc)
{
    cudaFuncSetAttribute(gemm_mma<EPI>,
                         cudaFuncAttributeMaxDynamicSharedMemorySize, GEMM_SMEM);
    dim3 grid(N / 128, M / 128, 1);
    gemm_mma<EPI><<<grid, 256, GEMM_SMEM>>>(A, B, bias, C, M, N, K, lda, ldb, ldc);
}

extern "C" void kernel_launch(void* const* d_in, const int* in_sizes, int n_in,
                              void* d_out, int out_size)
{
    const float* bm   = (const float*)d_in[0];
    const float* h0   = (const float*)d_in[1];
    const float* Wp   = (const float*)d_in[2];
    const float* bp   = (const float*)d_in[3];
    const float* ln1g = (const float*)d_in[4];
    const float* ln1b = (const float*)d_in[5];
    const float* Wqkv = (const float*)d_in[6];
    const float* bqkv = (const float*)d_in[7];
    const float* Wo   = (const float*)d_in[8];
    const float* bo   = (const float*)d_in[9];
    const float* ln2g = (const float*)d_in[10];
    const float* ln2b = (const float*)d_in[11];
    const float* W1   = (const float*)d_in[12];
    const float* b1   = (const float*)d_in[13];
    const float* W2   = (const float*)d_in[14];
    const float* b2   = (const float*)d_in[15];
    const float* Wi2h = (const float*)d_in[16];
    const float* bi2h = (const float*)d_in[17];
    const float* Wh2o = (const float*)d_in[18];
    const float* bh2o = (const float*)d_in[19];
    const float* Wc   = (const float*)d_in[20];
    const float* bc   = (const float*)d_in[21];
    float* out = (float*)d_out;

    float *px, *pa, *pq, *po, *pf, *pxp, *ph;
    cudaGetSymbolAddress((void**)&px,  g_x);
    cudaGetSymbolAddress((void**)&pa,  g_a);
    cudaGetSymbolAddress((void**)&pq,  g_qkv);
    cudaGetSymbolAddress((void**)&po,  g_o);
    cudaGetSymbolAddress((void**)&pf,  g_f);
    cudaGetSymbolAddress((void**)&pxp, g_xp);
    cudaGetSymbolAddress((void**)&ph,  g_h);

    cudaFuncSetAttribute(flash_kernel,
                         cudaFuncAttributeMaxDynamicSharedMemorySize, FL_SMEM);

    // 1) modality projection: x = bm @ Wp^T + bp
    run_mm<0>(bm, Wp, bp, px, MTOK, EE, DIN, DIN, DIN, EE);

    for (int l = 0; l < LL; l++) {
        const float* wqkv = Wqkv + (size_t)l * 3 * EE * EE;
        const float* bqk  = bqkv + (size_t)l * 3 * EE;
        const float* wo   = Wo   + (size_t)l * EE * EE;
        const float* bo_  = bo   + (size_t)l * EE;
        const float* w1   = W1   + (size_t)l * FF * EE;
        const float* b1_  = b1   + (size_t)l * FF;
        const float* w2   = W2   + (size_t)l * EE * FF;
        const float* b2_  = b2   + (size_t)l * EE;

        // pre-LN attention
        ln_kernel<<<MTOK, 128>>>(px, ln1g + l * EE, ln1b + l * EE, pa);
        run_mm<0>(pa, wqkv, bqk, pq, MTOK, 3 * EE, EE, EE, EE, 3 * EE);

        // fused flash attention: qkv -> o
        {
            dim3 grid(SS / 128, BB * HH);
            flash_kernel<<<grid, 256, FL_SMEM>>>(pq, po);
        }

        // x += O @ Wo^T + bo
        run_mm<2>(po, wo, bo_, px, MTOK, EE, EE, EE, EE, EE);

        // pre-LN FFN
        ln_kernel<<<MTOK, 128>>>(px, ln2g + l * EE, ln2b + l * EE, pa);
        run_mm<1>(pa, w1, b1_, pf, MTOK, FF, EE, EE, EE, FF);
        run_mm<2>(pf, w2, b2_, px, MTOK, EE, FF, FF, FF, EE);
    }

    // recurrence x-part: xp = x @ Wi2h[:, :E]^T + bi2h   (ldb = 2E)
    run_mm<0>(px, Wi2h, bi2h, pxp, MTOK, EE, EE, EE, 2 * EE, EE);

    // sequential recurrence (persistent, clustered)
    recur_kernel<<<128, 256>>>(pxp, h0, Wi2h, ph);

    // head: logits + sigmoid
    head_kernel<<<BB, 512>>>(ph, Wh2o, bh2o, Wc, bc, out, out_size / 2);
}

// round 7
// speedup vs baseline: 2.6384x; 1.0153x over previous
#include <cuda_runtime.h>
#include <cuda_bf16.h>
#include <math.h>
#include <stdint.h>

// ---------------- problem constants ----------------
#define BB   16
#define SS   1024
#define DIN  768
#define EE   512
#define HH   8
#define LL   2
#define FF   2048
#define DH   64
#define MTOK (BB*SS)          // 16384 rows

// ---------------- scratch ----------------
__device__ float g_x  [MTOK*EE];
__device__ float g_a  [MTOK*EE];
__device__ float g_qkv[MTOK*3*EE];
__device__ float g_o  [MTOK*EE];
__device__ float g_f  [MTOK*FF];
__device__ float g_xp [MTOK*EE];
__device__ float g_h  [BB*EE];

// ---------------- helpers ----------------
__device__ __forceinline__ float gelu_exact(float x) {
    return 0.5f * x * (1.0f + erff(x * 0.7071067811865476f));
}
__device__ __forceinline__ uint32_t swz128(uint32_t off) {
    return off ^ ((off >> 3) & 0x70);
}
__device__ __forceinline__ void cpasync16(uint32_t dst, const void* src) {
    asm volatile("cp.async.cg.shared.global [%0], [%1], 16;" :: "r"(dst), "l"(src));
}
__device__ __forceinline__ void cp_commit() { asm volatile("cp.async.commit_group;"); }
__device__ __forceinline__ void cp_wait1() { asm volatile("cp.async.wait_group 1;"); }
__device__ __forceinline__ void cp_wait0() { asm volatile("cp.async.wait_group 0;"); }
__device__ __forceinline__ uint32_t smem_u32(const void* p) {
    uint32_t a;
    asm("{ .reg .u64 t; cvta.to.shared.u64 t, %1; cvt.u32.u64 %0, t; }" : "=r"(a) : "l"(p));
    return a;
}
__device__ __forceinline__ uint32_t f2tf(float f) {
    uint32_t u;
    asm("cvt.rna.tf32.f32 %0, %1;" : "=r"(u) : "f"(f));
    return u;
}
__device__ __forceinline__ float lds_swz(const char* base, int row, int col) {
    return *(const float*)(base + row * 128 + ((col * 4) ^ ((row & 7) << 4)));
}
__device__ __forceinline__ void mma_tf32(float* c, const uint32_t* a, const uint32_t* b) {
    asm volatile(
        "mma.sync.aligned.m16n8k8.row.col.f32.tf32.tf32.f32 "
        "{%0,%1,%2,%3}, {%4,%5,%6,%7}, {%8,%9}, {%0,%1,%2,%3};"
        : "+f"(c[0]), "+f"(c[1]), "+f"(c[2]), "+f"(c[3])
        : "r"(a[0]), "r"(a[1]), "r"(a[2]), "r"(a[3]), "r"(b[0]), "r"(b[1]));
}

// =====================================================================
// tf32 warp-MMA GEMM: C[M,N] = epi( A[M,K] * B^T + bias )
//   A row-major [M,K] lda; B [N,K] ldb (weight layout).
//   CTA tile 128x128, 256 threads (4x2 warps), K chunk 32, 3-stage pipe.
//   EPI: 0=bias, 1=bias+gelu, 2=C += acc + bias
// =====================================================================
template<int EPI>
__global__ void __launch_bounds__(256, 2)
gemm_mma(const float* __restrict__ A, const float* __restrict__ B,
         const float* __restrict__ bias, float* __restrict__ C,
         int M, int N, int K, int lda, int ldb, int ldc)
{
    extern __shared__ char smem[];
    constexpr int ASZ = 128 * 32 * 4;   // 16 KB per stage
    constexpr int BSZ = 128 * 32 * 4;
    const uint32_t sb = smem_u32(smem);

    const int tid = threadIdx.x;
    const int wid = tid >> 5;
    const int lane = tid & 31;
    const int g  = lane >> 2;
    const int tg = lane & 3;
    const int wm = wid & 3;
    const int wn = wid >> 2;
    const int bm = blockIdx.y * 128;
    const int bn = blockIdx.x * 128;

    const int NC = K >> 5;

    float acc[2][8][4];
    #pragma unroll
    for (int i = 0; i < 2; i++)
        #pragma unroll
        for (int j = 0; j < 8; j++)
            #pragma unroll
            for (int q = 0; q < 4; q++) acc[i][j][q] = 0.f;

    auto loadA = [&](int stage, int k0) {
        uint32_t base = sb + stage * (ASZ + BSZ);
        const float* src0 = A + (long long)bm * lda + k0;
        #pragma unroll
        for (int i = 0; i < 4; i++) {
            int j = tid + i * 256;
            int row = j >> 3;
            int c4  = (j & 7) * 4;
            cpasync16(base + swz128(row * 128 + c4 * 4),
                      src0 + (long long)row * lda + c4);
        }
    };
    auto loadB = [&](int stage, int k0) {
        uint32_t base = sb + stage * (ASZ + BSZ) + ASZ;
        const float* src0 = B + (long long)bn * ldb + k0;
        #pragma unroll
        for (int i = 0; i < 4; i++) {
            int j = tid + i * 256;
            int row = j >> 3;
            int c4  = (j & 7) * 4;
            cpasync16(base + swz128(row * 128 + c4 * 4),
                      src0 + (long long)row * ldb + c4);
        }
    };

    auto compute = [&](int stage) {
        const char* Ab = smem + stage * (ASZ + BSZ);
        const char* Bb = Ab + ASZ;
        #pragma unroll
        for (int kk = 0; kk < 4; kk++) {
            const int k0 = kk * 8;
            uint32_t afr[2][4];
            #pragma unroll
            for (int ma = 0; ma < 2; ma++) {
                int r0 = wm * 32 + ma * 16 + g;
                afr[ma][0] = f2tf(lds_swz(Ab, r0,     k0 + tg));
                afr[ma][1] = f2tf(lds_swz(Ab, r0 + 8, k0 + tg));
                afr[ma][2] = f2tf(lds_swz(Ab, r0,     k0 + tg + 4));
                afr[ma][3] = f2tf(lds_swz(Ab, r0 + 8, k0 + tg + 4));
            }
            uint32_t bfr[8][2];
            #pragma unroll
            for (int na = 0; na < 8; na++) {
                int rn = wn * 64 + na * 8 + g;
                bfr[na][0] = f2tf(lds_swz(Bb, rn, k0 + tg));
                bfr[na][1] = f2tf(lds_swz(Bb, rn, k0 + tg + 4));
            }
            #pragma unroll
            for (int ma = 0; ma < 2; ma++)
                #pragma unroll
                for (int na = 0; na < 8; na++)
                    mma_tf32(acc[ma][na], afr[ma], bfr[na]);
        }
    };

    // ---------- 3-stage pipelined mainloop ----------
    loadA(0, 0); loadB(0, 0); cp_commit();
    loadA(1, 32); loadB(1, 32); cp_commit();
    for (int c = 0; c < NC; c++) {
        if (c + 1 < NC) cp_wait1(); else cp_wait0();
        __syncthreads();
        if (c + 2 < NC) {
            int s = (c + 2) % 3;
            loadA(s, (c + 2) << 5); loadB(s, (c + 2) << 5); cp_commit();
        }
        compute(c % 3);
    }

    // ---------- epilogue ----------
    #pragma unroll
    for (int ma = 0; ma < 2; ma++) {
        int row0 = bm + wm * 32 + ma * 16 + g;
        #pragma unroll
        for (int na = 0; na < 8; na++) {
            int col = bn + wn * 64 + na * 8 + tg * 2;
            #pragma unroll
            for (int half = 0; half < 2; half++) {
                int row = row0 + half * 8;
                float2 v;
                v.x = acc[ma][na][half * 2 + 0];
                v.y = acc[ma][na][half * 2 + 1];
                if (bias) { v.x += bias[col]; v.y += bias[col + 1]; }
                if (EPI == 1) { v.x = gelu_exact(v.x); v.y = gelu_exact(v.y); }
                long long ro = (long long)row * ldc + col;
                if (EPI == 2) {
                    float2 old = *(const float2*)(C + ro);
                    v.x += old.x; v.y += old.y;
                }
                *(float2*)(C + ro) = v;
            }
        }
    }
}

// =====================================================================
// Fused flash attention v2 (tf32). One CTA per (q-tile 128, b*H+h).
// KV tile = 64 rows (16 j-iterations) -> half the smem/regs of v1 so
// TWO CTAs fit per SM. 256 threads = 8 warps; warp w owns q rows
// w*16+{g,g+8}. Strides: K 68 fl, V 72 fl, P 68 fl (conflict-free reads).
// =====================================================================
#define KTI 64
#define KST 68
#define VST 72
#define PST 68
#define FKSZ (KTI*KST*4)
#define FVSZ (KTI*VST*4)
#define FL_SMEM (2*FKSZ + 2*FVSZ + 128*PST*4)

__global__ void __launch_bounds__(256, 2)
flash_kernel(const float* __restrict__ qkv, float* __restrict__ o)
{
    extern __shared__ char fs[];
    const int tid = threadIdx.x;
    const int w = tid >> 5, lane = tid & 31;
    const int g = lane >> 2, tg = lane & 3;
    const int qt = blockIdx.x;            // q tile 0..7
    const int z  = blockIdx.y;            // b*H + h
    const int bb = z >> 3, hh = z & 7;

    char* Ks = fs;
    char* Vs = fs + 2 * FKSZ;
    float* Ps = (float*)(fs + 2 * FKSZ + 2 * FVSZ);
    const uint32_t Ksb = smem_u32(Ks), Vsb = smem_u32(Vs);

    const float* qbase = qkv + (size_t)bb * SS * (3 * EE) + hh * DH;

    // ---- Q fragments in registers, pre-scaled by 1/sqrt(DH) ----
    uint32_t qfr[8][4];
    {
        int r0 = qt * 128 + w * 16 + g;
        const float* q0 = qbase + (size_t)r0 * (3 * EE);
        const float* q1 = q0 + (size_t)8 * (3 * EE);
        #pragma unroll
        for (int kk = 0; kk < 8; kk++) {
            qfr[kk][0] = f2tf(0.125f * q0[kk * 8 + tg]);
            qfr[kk][1] = f2tf(0.125f * q1[kk * 8 + tg]);
            qfr[kk][2] = f2tf(0.125f * q0[kk * 8 + tg + 4]);
            qfr[kk][3] = f2tf(0.125f * q1[kk * 8 + tg + 4]);
        }
    }

    float m0 = -1e30f, m1 = -1e30f, l0 = 0.f, l1 = 0.f;
    float oacc[8][4];
    #pragma unroll
    for (int i = 0; i < 8; i++)
        #pragma unroll
        for (int q = 0; q < 4; q++) oacc[i][q] = 0.f;

    auto loadKV = [&](int st, int j) {
        const float* kg = qbase + EE     + (size_t)(j * KTI) * (3 * EE);
        const float* vg = qbase + 2 * EE + (size_t)(j * KTI) * (3 * EE);
        #pragma unroll
        for (int i = 0; i < 4; i++) {
            int idx = tid + i * 256;            // 0..1023
            int row = idx >> 4, c4 = (idx & 15) * 4;
            cpasync16(Ksb + st * FKSZ + (row * KST + c4) * 4,
                      kg + (size_t)row * (3 * EE) + c4);
            cpasync16(Vsb + st * FVSZ + (row * VST + c4) * 4,
                      vg + (size_t)row * (3 * EE) + c4);
        }
    };

    loadKV(0, 0); cp_commit();

    const int prow0 = (w * 16 + g) * PST;
    const int prow1 = prow0 + 8 * PST;

    for (int j = 0; j < 16; j++) {
        cp_wait0();
        __syncthreads();                     // KV(j) landed; PV(j-1) done everywhere
        if (j + 1 < 16) { loadKV((j + 1) & 1, j + 1); cp_commit(); }

        // ---- S = Q K^T (sacc[na] covers cols na*8 + {2tg, 2tg+1}) ----
        float sacc[8][4];
        #pragma unroll
        for (int na = 0; na < 8; na++)
            #pragma unroll
            for (int q = 0; q < 4; q++) sacc[na][q] = 0.f;

        const float* Kt = (const float*)(Ks + (j & 1) * FKSZ);
        #pragma unroll
        for (int kk = 0; kk < 8; kk++) {
            #pragma unroll
            for (int na = 0; na < 8; na++) {
                int rn = na * 8 + g;
                uint32_t bfr[2];
                bfr[0] = f2tf(Kt[rn * KST + kk * 8 + tg]);
                bfr[1] = f2tf(Kt[rn * KST + kk * 8 + tg + 4]);
                mma_tf32(sacc[na], qfr[kk], bfr);
            }
        }

        // ---- online softmax ----
        float mx0 = -1e30f, mx1 = -1e30f;
        #pragma unroll
        for (int na = 0; na < 8; na++) {
            mx0 = fmaxf(mx0, fmaxf(sacc[na][0], sacc[na][1]));
            mx1 = fmaxf(mx1, fmaxf(sacc[na][2], sacc[na][3]));
        }
        mx0 = fmaxf(mx0, __shfl_xor_sync(0xffffffffu, mx0, 1));
        mx0 = fmaxf(mx0, __shfl_xor_sync(0xffffffffu, mx0, 2));
        mx1 = fmaxf(mx1, __shfl_xor_sync(0xffffffffu, mx1, 1));
        mx1 = fmaxf(mx1, __shfl_xor_sync(0xffffffffu, mx1, 2));
        float nm0 = fmaxf(m0, mx0), nm1 = fmaxf(m1, mx1);
        float a0 = expf(m0 - nm0), a1 = expf(m1 - nm1);
        float rs0 = 0.f, rs1 = 0.f;
        #pragma unroll
        for (int na = 0; na < 8; na++) {
            float p00 = expf(sacc[na][0] - nm0);
            float p01 = expf(sacc[na][1] - nm0);
            float p10 = expf(sacc[na][2] - nm1);
            float p11 = expf(sacc[na][3] - nm1);
            rs0 += p00 + p01; rs1 += p10 + p11;
            int col = na * 8 + tg * 2;
            *(float2*)(Ps + prow0 + col) = make_float2(p00, p01);
            *(float2*)(Ps + prow1 + col) = make_float2(p10, p11);
        }
        rs0 += __shfl_xor_sync(0xffffffffu, rs0, 1);
        rs0 += __shfl_xor_sync(0xffffffffu, rs0, 2);
        rs1 += __shfl_xor_sync(0xffffffffu, rs1, 1);
        rs1 += __shfl_xor_sync(0xffffffffu, rs1, 2);
        l0 = l0 * a0 + rs0; l1 = l1 * a1 + rs1;
        m0 = nm0; m1 = nm1;
        #pragma unroll
        for (int na2 = 0; na2 < 8; na2++) {
            oacc[na2][0] *= a0; oacc[na2][1] *= a0;
            oacc[na2][2] *= a1; oacc[na2][3] *= a1;
        }
        __syncthreads();                    // all warps' P writes visible

        // ---- O += P V ----
        const float* Vt = (const float*)(Vs + (j & 1) * FVSZ);
        #pragma unroll
        for (int kk = 0; kk < 8; kk++) {
            uint32_t pf[4];
            pf[0] = f2tf(Ps[prow0 + kk * 8 + tg]);
            pf[1] = f2tf(Ps[prow1 + kk * 8 + tg]);
            pf[2] = f2tf(Ps[prow0 + kk * 8 + tg + 4]);
            pf[3] = f2tf(Ps[prow1 + kk * 8 + tg + 4]);
            #pragma unroll
            for (int na2 = 0; na2 < 8; na2++) {
                uint32_t bf[2];
                bf[0] = f2tf(Vt[(kk * 8 + tg) * VST + na2 * 8 + g]);
                bf[1] = f2tf(Vt[(kk * 8 + tg + 4) * VST + na2 * 8 + g]);
                mma_tf32(oacc[na2], pf, bf);
            }
        }
    }

    // ---- epilogue: O / l -> gmem ----
    float inv0 = 1.f / l0, inv1 = 1.f / l1;
    int r0 = qt * 128 + w * 16 + g;
    float* ob0 = o + (size_t)(bb * SS + r0) * EE + hh * DH;
    float* ob1 = ob0 + (size_t)8 * EE;
    #pragma unroll
    for (int na2 = 0; na2 < 8; na2++) {
        int col = na2 * 8 + tg * 2;
        *(float2*)(ob0 + col) = make_float2(oacc[na2][0] * inv0, oacc[na2][1] * inv0);
        *(float2*)(ob1 + col) = make_float2(oacc[na2][2] * inv1, oacc[na2][3] * inv1);
    }
}

// =====================================================================
// LayerNorm over last dim (512). One CTA (128 threads) per row.
// =====================================================================
__global__ void ln_kernel(const float* __restrict__ x, const float* __restrict__ g,
                          const float* __restrict__ b, float* __restrict__ y)
{
    long long row = blockIdx.x;
    const float* xr = x + row * EE;
    int tid = threadIdx.x;
    float4 v = *(const float4*)(xr + tid * 4);
    float s  = v.x + v.y + v.z + v.w;
    float s2 = v.x * v.x + v.y * v.y + v.z * v.z + v.w * v.w;
    #pragma unroll
    for (int o = 16; o > 0; o >>= 1) {
        s  += __shfl_xor_sync(0xffffffffu, s, o);
        s2 += __shfl_xor_sync(0xffffffffu, s2, o);
    }
    __shared__ float ss[4], ssq[4];
    int w = tid >> 5, l = tid & 31;
    if (l == 0) { ss[w] = s; ssq[w] = s2; }
    __syncthreads();
    s  = ss[0] + ss[1] + ss[2] + ss[3];
    s2 = ssq[0] + ssq[1] + ssq[2] + ssq[3];
    float m   = s * (1.0f / EE);
    float var = s2 * (1.0f / EE) - m * m;
    float inv = rsqrtf(var + 1e-5f);
    float4 gg = *(const float4*)(g + tid * 4);
    float4 bb = *(const float4*)(b + tid * 4);
    float4 o4;
    o4.x = (v.x - m) * inv * gg.x + bb.x;
    o4.y = (v.y - m) * inv * gg.y + bb.y;
    o4.z = (v.z - m) * inv * gg.z + bb.z;
    o4.w = (v.w - m) * inv * gg.w + bb.w;
    *(float4*)(y + row * EE + tid * 4) = o4;
}

// =====================================================================
// Mamba-style recurrence. 4-way split accumulators break the 128-deep
// dependent FFMA chain (512 -> ~130 cyc per step).
// =====================================================================
__global__ void __cluster_dims__(8, 1, 1) __launch_bounds__(256, 1)
recur_kernel(const float* __restrict__ XP, const float* __restrict__ h0,
             const float* __restrict__ Wi2h, float* __restrict__ hout)
{
    __shared__ float hbuf[2 * EE];
    __shared__ float partial[256];

    const int tid = threadIdx.x;
    const int b = blockIdx.x >> 3;
    const int r = blockIdx.x & 7;
    const int part = tid >> 6;
    const int e    = tid & 63;

    float4 w[32];
    {
        const float* wsrc = Wi2h + (long long)(r * 64 + e) * (2 * EE) + EE + part * 128;
        #pragma unroll
        for (int i = 0; i < 32; i++) w[i] = *(const float4*)(wsrc + i * 4);
    }
    if (tid < 128) *(float4*)(hbuf + tid * 4) = *(const float4*)(h0 + b * EE + tid * 4);

    uint32_t hb = (uint32_t)__cvta_generic_to_shared(hbuf);
    __syncthreads();
    asm volatile("barrier.cluster.arrive.aligned;" ::: "memory");
    asm volatile("barrier.cluster.wait.aligned;"   ::: "memory");

    const long long xpbase = (long long)b * SS * EE + r * 64 + e;

    for (int t = 0; t < SS; t++) {
        float xpv = 0.f;
        if (tid < 64) xpv = __ldg(XP + xpbase + (long long)t * EE);

        const float* hr = hbuf + (t & 1) * EE + part * 128;
        float a0 = 0.f, a1 = 0.f, a2 = 0.f, a3 = 0.f;
        #pragma unroll
        for (int i = 0; i < 32; i++) {
            float4 h4 = *(const float4*)(hr + i * 4);
            a0 += w[i].x * h4.x; a1 += w[i].y * h4.y;
            a2 += w[i].z * h4.z; a3 += w[i].w * h4.w;
        }
        partial[part * 64 + e] = (a0 + a1) + (a2 + a3);
        __syncthreads();

        if (tid < 64) {
            float sm = partial[e] + partial[64 + e] + partial[128 + e] + partial[192 + e] + xpv;
            float hn = tanhf(sm);
            hn = (hn > 0.f) ? hn : 0.f;
            uint32_t loff = hb + (uint32_t)((((t + 1) & 1) * EE + r * 64 + e) * 4);
            #pragma unroll
            for (int c = 0; c < 8; c++) {
                uint32_t ra;
                asm("mapa.shared::cluster.u32 %0, %1, %2;" : "=r"(ra) : "r"(loff), "r"(c));
                asm volatile("st.shared::cluster.f32 [%0], %1;" :: "r"(ra), "f"(hn));
            }
        }
        asm volatile("barrier.cluster.arrive.aligned;" ::: "memory");
        asm volatile("barrier.cluster.wait.aligned;"   ::: "memory");
    }
    if (tid < 64) hout[b * EE + r * 64 + e] = hbuf[r * 64 + e];
}

// =====================================================================
// Head (unchanged).
// =====================================================================
__global__ void head_kernel(const float* __restrict__ hfin, const float* __restrict__ Wh2o,
                            const float* __restrict__ bh2o, const float* __restrict__ Wc,
                            const float* __restrict__ bc, float* __restrict__ out, int half)
{
    int b = blockIdx.x, tid = threadIdx.x;
    __shared__ float hrow[EE];
    __shared__ float red[EE];
    hrow[tid] = hfin[b * EE + tid];
    __syncthreads();
    const float* wr = Wh2o + (long long)tid * EE;
    float acc = bh2o[tid];
    #pragma unroll 8
    for (int f = 0; f < EE; f += 4) {
        float4 w4 = *(const float4*)(wr + f);
        acc += w4.x * hrow[f] + w4.y * hrow[f + 1] + w4.z * hrow[f + 2] + w4.w * hrow[f + 3];
    }
    red[tid] = acc * Wc[tid];
    __syncthreads();
    for (int s = 256; s > 0; s >>= 1) {
        if (tid < s) red[tid] += red[tid + s];
        __syncthreads();
    }
    if (tid == 0) {
        float lg = red[0] + bc[0];
        out[b] = lg;
        out[half + b] = 1.f / (1.f + expf(-lg));
    }
}

// ---------------- host-side launch helpers ----------------
static const int GEMM_SMEM = 3 * (128 * 32 * 4 + 128 * 32 * 4);  // 98304

template<int EPI>
static void run_mm(const float* A, const float* B, const float* bias, float* C,
                   int M, int N, int K, int lda, int ldb, int ldc)
{
    cudaFuncSetAttribute(gemm_mma<EPI>,
                         cudaFuncAttributeMaxDynamicSharedMemorySize, GEMM_SMEM);
    dim3 grid(N / 128, M / 128, 1);
    gemm_mma<EPI><<<grid, 256, GEMM_SMEM>>>(A, B, bias, C, M, N, K, lda, ldb, ldc);
}

extern "C" void kernel_launch(void* const* d_in, const int* in_sizes, int n_in,
                              void* d_out, int out_size)
{
    const float* bm   = (const float*)d_in[0];
    const float* h0   = (const float*)d_in[1];
    const float* Wp   = (const float*)d_in[2];
    const float* bp   = (const float*)d_in[3];
    const float* ln1g = (const float*)d_in[4];
    const float* ln1b = (const float*)d_in[5];
    const float* Wqkv = (const float*)d_in[6];
    const float* bqkv = (const float*)d_in[7];
    const float* Wo   = (const float*)d_in[8];
    const float* bo   = (const float*)d_in[9];
    const float* ln2g = (const float*)d_in[10];
    const float* ln2b = (const float*)d_in[11];
    const float* W1   = (const float*)d_in[12];
    const float* b1   = (const float*)d_in[13];
    const float* W2   = (const float*)d_in[14];
    const float* b2   = (const float*)d_in[15];
    const float* Wi2h = (const float*)d_in[16];
    const float* bi2h = (const float*)d_in[17];
    const float* Wh2o = (const float*)d_in[18];
    const float* bh2o = (const float*)d_in[19];
    const float* Wc   = (const float*)d_in[20];
    const float* bc   = (const float*)d_in[21];
    float* out = (float*)d_out;

    float *px, *pa, *pq, *po, *pf, *pxp, *ph;
    cudaGetSymbolAddress((void**)&px,  g_x);
    cudaGetSymbolAddress((void**)&pa,  g_a);
    cudaGetSymbolAddress((void**)&pq,  g_qkv);
    cudaGetSymbolAddress((void**)&po,  g_o);
    cudaGetSymbolAddress((void**)&pf,  g_f);
    cudaGetSymbolAddress((void**)&pxp, g_xp);
    cudaGetSymbolAddress((void**)&ph,  g_h);

    cudaFuncSetAttribute(flash_kernel,
                         cudaFuncAttributeMaxDynamicSharedMemorySize, FL_SMEM);

    // 1) modality projection: x = bm @ Wp^T + bp
    run_mm<0>(bm, Wp, bp, px, MTOK, EE, DIN, DIN, DIN, EE);

    for (int l = 0; l < LL; l++) {
        const float* wqkv = Wqkv + (size_t)l * 3 * EE * EE;
        const float* bqk  = bqkv + (size_t)l * 3 * EE;
        const float* wo   = Wo   + (size_t)l * EE * EE;
        const float* bo_  = bo   + (size_t)l * EE;
        const float* w1   = W1   + (size_t)l * FF * EE;
        const float* b1_  = b1   + (size_t)l * FF;
        const float* w2   = W2   + (size_t)l * EE * FF;
        const float* b2_  = b2   + (size_t)l * EE;

        // pre-LN attention
        ln_kernel<<<MTOK, 128>>>(px, ln1g + l * EE, ln1b + l * EE, pa);
        run_mm<0>(pa, wqkv, bqk, pq, MTOK, 3 * EE, EE, EE, EE, 3 * EE);

        // fused flash attention: qkv -> o
        {
            dim3 grid(SS / 128, BB * HH);
            flash_kernel<<<grid, 256, FL_SMEM>>>(pq, po);
        }

        // x += O @ Wo^T + bo
        run_mm<2>(po, wo, bo_, px, MTOK, EE, EE, EE, EE, EE);

        // pre-LN FFN
        ln_kernel<<<MTOK, 128>>>(px, ln2g + l * EE, ln2b + l * EE, pa);
        run_mm<1>(pa, w1, b1_, pf, MTOK, FF, EE, EE, EE, FF);
        run_mm<2>(pf, w2, b2_, px, MTOK, EE, FF, FF, FF, EE);
    }

    // recurrence x-part: xp = x @ Wi2h[:, :E]^T + bi2h   (ldb = 2E)
    run_mm<0>(px, Wi2h, bi2h, pxp, MTOK, EE, EE, EE, 2 * EE, EE);

    // sequential recurrence (persistent, clustered)
    recur_kernel<<<128, 256>>>(pxp, h0, Wi2h, ph);

    // head: logits + sigmoid
    head_kernel<<<BB, 512>>>(ph, Wh2o, bh2o, Wc, bc, out, out_size / 2);
}

// round 8
// speedup vs baseline: 2.9039x; 1.1006x over previous
#include <cuda_runtime.h>
#include <cuda_bf16.h>
#include <math.h>
#include <stdint.h>

// ---------------- problem constants ----------------
#define BB   16
#define SS   1024
#define DIN  768
#define EE   512
#define HH   8
#define LL   2
#define FF   2048
#define DH   64
#define MTOK (BB*SS)          // 16384 rows

// ---------------- scratch ----------------
__device__ float g_x  [MTOK*EE];
__device__ float g_a  [MTOK*EE];
__device__ float g_qkv[MTOK*3*EE];
__device__ float g_o  [MTOK*EE];
__device__ float g_f  [MTOK*FF];
__device__ float g_xp [MTOK*EE];
__device__ float g_h  [BB*EE];
__device__ float g_wr [7208960];        // tf32-rounded weight copies

// rounded-weight offsets
#define OFF_WP   0
#define OFF_WQKV 393216
#define OFF_WO   1966080
#define OFF_W1   2490368
#define OFF_W2   4587520
#define OFF_WI   6684672

// ---------------- helpers ----------------
__device__ __forceinline__ float gelu_exact(float x) {
    return 0.5f * x * (1.0f + erff(x * 0.7071067811865476f));
}
__device__ __forceinline__ uint32_t swz128(uint32_t off) {
    return off ^ ((off >> 3) & 0x70);
}
__device__ __forceinline__ void cpasync16(uint32_t dst, const void* src) {
    asm volatile("cp.async.cg.shared.global [%0], [%1], 16;" :: "r"(dst), "l"(src));
}
__device__ __forceinline__ void cp_commit() { asm volatile("cp.async.commit_group;"); }
__device__ __forceinline__ void cp_wait1() { asm volatile("cp.async.wait_group 1;"); }
__device__ __forceinline__ void cp_wait0() { asm volatile("cp.async.wait_group 0;"); }
__device__ __forceinline__ uint32_t smem_u32(const void* p) {
    uint32_t a;
    asm("{ .reg .u64 t; cvta.to.shared.u64 t, %1; cvt.u32.u64 %0, t; }" : "=r"(a) : "l"(p));
    return a;
}
__device__ __forceinline__ uint32_t f2tf(float f) {
    uint32_t u;
    asm("cvt.rna.tf32.f32 %0, %1;" : "=r"(u) : "f"(f));
    return u;
}
__device__ __forceinline__ float roundtf(float f) {
    return __uint_as_float(f2tf(f));
}
__device__ __forceinline__ float lds_swz(const char* base, int row, int col) {
    return *(const float*)(base + row * 128 + ((col * 4) ^ ((row & 7) << 4)));
}
__device__ __forceinline__ void mma_tf32(float* c, const uint32_t* a, const uint32_t* b) {
    asm volatile(
        "mma.sync.aligned.m16n8k8.row.col.f32.tf32.tf32.f32 "
        "{%0,%1,%2,%3}, {%4,%5,%6,%7}, {%8,%9}, {%0,%1,%2,%3};"
        : "+f"(c[0]), "+f"(c[1]), "+f"(c[2]), "+f"(c[3])
        : "r"(a[0]), "r"(a[1]), "r"(a[2]), "r"(a[3]), "r"(b[0]), "r"(b[1]));
}

// =====================================================================
// Weight pre-rounding: dst = tf32_round(src), elementwise.
// =====================================================================
__global__ void round_kernel(const float* __restrict__ src, float* __restrict__ dst, int n)
{
    int i = blockIdx.x * 256 + threadIdx.x;
    if (i < n) dst[i] = roundtf(src[i]);
}

// =====================================================================
// tf32 warp-MMA GEMM: C[M,N] = epi( A[M,K] * B^T + bias )
//   B is ALWAYS pre-rounded to tf32 bits (g_wr copies) -> raw loads.
//   CVTA: cvt A fragments in-loop (for raw f32 A); else A pre-rounded.
//   RND : round outputs to tf32 bits (when C feeds a later GEMM/flash A).
//   EPI : 0=bias, 1=bias+gelu, 2=C += acc + bias
// =====================================================================
template<int EPI, bool CVTA, bool RND>
__global__ void __launch_bounds__(256, 2)
gemm_mma(const float* __restrict__ A, const float* __restrict__ B,
         const float* __restrict__ bias, float* __restrict__ C,
         int M, int N, int K, int lda, int ldb, int ldc)
{
    extern __shared__ char smem[];
    constexpr int ASZ = 128 * 32 * 4;
    constexpr int BSZ = 128 * 32 * 4;
    const uint32_t sb = smem_u32(smem);

    const int tid = threadIdx.x;
    const int wid = tid >> 5;
    const int lane = tid & 31;
    const int g  = lane >> 2;
    const int tg = lane & 3;
    const int wm = wid & 3;
    const int wn = wid >> 2;
    const int bm = blockIdx.y * 128;
    const int bn = blockIdx.x * 128;

    const int NC = K >> 5;

    float acc[2][8][4];
    #pragma unroll
    for (int i = 0; i < 2; i++)
        #pragma unroll
        for (int j = 0; j < 8; j++)
            #pragma unroll
            for (int q = 0; q < 4; q++) acc[i][j][q] = 0.f;

    auto loadA = [&](int stage, int k0) {
        uint32_t base = sb + stage * (ASZ + BSZ);
        const float* src0 = A + (long long)bm * lda + k0;
        #pragma unroll
        for (int i = 0; i < 4; i++) {
            int j = tid + i * 256;
            int row = j >> 3;
            int c4  = (j & 7) * 4;
            cpasync16(base + swz128(row * 128 + c4 * 4),
                      src0 + (long long)row * lda + c4);
        }
    };
    auto loadB = [&](int stage, int k0) {
        uint32_t base = sb + stage * (ASZ + BSZ) + ASZ;
        const float* src0 = B + (long long)bn * ldb + k0;
        #pragma unroll
        for (int i = 0; i < 4; i++) {
            int j = tid + i * 256;
            int row = j >> 3;
            int c4  = (j & 7) * 4;
            cpasync16(base + swz128(row * 128 + c4 * 4),
                      src0 + (long long)row * ldb + c4);
        }
    };

    auto compute = [&](int stage) {
        const char* Ab = smem + stage * (ASZ + BSZ);
        const char* Bb = Ab + ASZ;
        #pragma unroll
        for (int kk = 0; kk < 4; kk++) {
            const int k0 = kk * 8;
            uint32_t afr[2][4];
            #pragma unroll
            for (int ma = 0; ma < 2; ma++) {
                int r0 = wm * 32 + ma * 16 + g;
                if (CVTA) {
                    afr[ma][0] = f2tf(lds_swz(Ab, r0,     k0 + tg));
                    afr[ma][1] = f2tf(lds_swz(Ab, r0 + 8, k0 + tg));
                    afr[ma][2] = f2tf(lds_swz(Ab, r0,     k0 + tg + 4));
                    afr[ma][3] = f2tf(lds_swz(Ab, r0 + 8, k0 + tg + 4));
                } else {
                    afr[ma][0] = __float_as_uint(lds_swz(Ab, r0,     k0 + tg));
                    afr[ma][1] = __float_as_uint(lds_swz(Ab, r0 + 8, k0 + tg));
                    afr[ma][2] = __float_as_uint(lds_swz(Ab, r0,     k0 + tg + 4));
                    afr[ma][3] = __float_as_uint(lds_swz(Ab, r0 + 8, k0 + tg + 4));
                }
            }
            uint32_t bfr[8][2];
            #pragma unroll
            for (int na = 0; na < 8; na++) {
                int rn = wn * 64 + na * 8 + g;
                bfr[na][0] = __float_as_uint(lds_swz(Bb, rn, k0 + tg));
                bfr[na][1] = __float_as_uint(lds_swz(Bb, rn, k0 + tg + 4));
            }
            #pragma unroll
            for (int ma = 0; ma < 2; ma++)
                #pragma unroll
                for (int na = 0; na < 8; na++)
                    mma_tf32(acc[ma][na], afr[ma], bfr[na]);
        }
    };

    // ---------- 3-stage pipelined mainloop ----------
    loadA(0, 0); loadB(0, 0); cp_commit();
    loadA(1, 32); loadB(1, 32); cp_commit();
    for (int c = 0; c < NC; c++) {
        if (c + 1 < NC) cp_wait1(); else cp_wait0();
        __syncthreads();
        if (c + 2 < NC) {
            int s = (c + 2) % 3;
            loadA(s, (c + 2) << 5); loadB(s, (c + 2) << 5); cp_commit();
        }
        compute(c % 3);
    }

    // ---------- epilogue ----------
    #pragma unroll
    for (int ma = 0; ma < 2; ma++) {
        int row0 = bm + wm * 32 + ma * 16 + g;
        #pragma unroll
        for (int na = 0; na < 8; na++) {
            int col = bn + wn * 64 + na * 8 + tg * 2;
            #pragma unroll
            for (int half = 0; half < 2; half++) {
                int row = row0 + half * 8;
                float2 v;
                v.x = acc[ma][na][half * 2 + 0];
                v.y = acc[ma][na][half * 2 + 1];
                if (bias) { v.x += bias[col]; v.y += bias[col + 1]; }
                if (EPI == 1) { v.x = gelu_exact(v.x); v.y = gelu_exact(v.y); }
                if (RND) { v.x = roundtf(v.x); v.y = roundtf(v.y); }
                long long ro = (long long)row * ldc + col;
                if (EPI == 2) {
                    float2 old = *(const float2*)(C + ro);
                    v.x += old.x; v.y += old.y;
                }
                *(float2*)(C + ro) = v;
            }
        }
    }
}

// =====================================================================
// Fused flash attention (tf32, pre-rounded QKV -> no cvt on Q/K/V).
// One CTA per (q-tile 128, b*H+h); KV tile 128 (8 j-iterations).
// 256 threads = 8 warps; warp w owns q rows w*16+{g,g+8}.
// K stride 68 fl, V stride 72 fl, P stride 132 fl (conflict-free reads).
// =====================================================================
#define KST 68
#define VST 72
#define PST 132
#define FKSZ (128*KST*4)
#define FVSZ (128*VST*4)
#define FL_SMEM (2*FKSZ + 2*FVSZ + 128*PST*4)

__global__ void __launch_bounds__(256, 1)
flash_kernel(const float* __restrict__ qkv, float* __restrict__ o)
{
    extern __shared__ char fs[];
    const int tid = threadIdx.x;
    const int w = tid >> 5, lane = tid & 31;
    const int g = lane >> 2, tg = lane & 3;
    const int qt = blockIdx.x;            // q tile 0..7
    const int z  = blockIdx.y;            // b*H + h
    const int bb = z >> 3, hh = z & 7;

    char* Ks = fs;
    char* Vs = fs + 2 * FKSZ;
    float* Ps = (float*)(fs + 2 * FKSZ + 2 * FVSZ);
    const uint32_t Ksb = smem_u32(Ks), Vsb = smem_u32(Vs);

    const float* qbase = qkv + (size_t)bb * SS * (3 * EE) + hh * DH;

    // ---- Q fragments (pre-rounded in gmem; x2^-3 scale is exact) ----
    uint32_t qfr[8][4];
    {
        int r0 = qt * 128 + w * 16 + g;
        const float* q0 = qbase + (size_t)r0 * (3 * EE);
        const float* q1 = q0 + (size_t)8 * (3 * EE);
        #pragma unroll
        for (int kk = 0; kk < 8; kk++) {
            qfr[kk][0] = __float_as_uint(0.125f * q0[kk * 8 + tg]);
            qfr[kk][1] = __float_as_uint(0.125f * q1[kk * 8 + tg]);
            qfr[kk][2] = __float_as_uint(0.125f * q0[kk * 8 + tg + 4]);
            qfr[kk][3] = __float_as_uint(0.125f * q1[kk * 8 + tg + 4]);
        }
    }

    float m0 = -1e30f, m1 = -1e30f, l0 = 0.f, l1 = 0.f;
    float oacc[8][4];
    #pragma unroll
    for (int i = 0; i < 8; i++)
        #pragma unroll
        for (int q = 0; q < 4; q++) oacc[i][q] = 0.f;

    auto loadKV = [&](int st, int j) {
        const float* kg = qbase + EE     + (size_t)(j * 128) * (3 * EE);
        const float* vg = qbase + 2 * EE + (size_t)(j * 128) * (3 * EE);
        #pragma unroll
        for (int i = 0; i < 8; i++) {
            int idx = tid + i * 256;            // 0..2047
            int row = idx >> 4, c4 = (idx & 15) * 4;
            cpasync16(Ksb + st * FKSZ + (row * KST + c4) * 4,
                      kg + (size_t)row * (3 * EE) + c4);
            cpasync16(Vsb + st * FVSZ + (row * VST + c4) * 4,
                      vg + (size_t)row * (3 * EE) + c4);
        }
    };

    loadKV(0, 0); cp_commit();

    const int prow0 = (w * 16 + g) * PST;
    const int prow1 = prow0 + 8 * PST;

    for (int j = 0; j < 8; j++) {
        cp_wait0();
        __syncthreads();                     // KV(j) landed; PV(j-1) done everywhere
        if (j + 1 < 8) { loadKV((j + 1) & 1, j + 1); cp_commit(); }

        // ---- S = Q K^T (sacc[na] covers cols na*8 + {2tg, 2tg+1}) ----
        float sacc[16][4];
        #pragma unroll
        for (int na = 0; na < 16; na++)
            #pragma unroll
            for (int q = 0; q < 4; q++) sacc[na][q] = 0.f;

        const float* Kt = (const float*)(Ks + (j & 1) * FKSZ);
        #pragma unroll
        for (int kk = 0; kk < 8; kk++) {
            #pragma unroll
            for (int na = 0; na < 16; na++) {
                int rn = na * 8 + g;
                uint32_t bfr[2];
                bfr[0] = __float_as_uint(Kt[rn * KST + kk * 8 + tg]);
                bfr[1] = __float_as_uint(Kt[rn * KST + kk * 8 + tg + 4]);
                mma_tf32(sacc[na], qfr[kk], bfr);
            }
        }

        // ---- online softmax ----
        float mx0 = -1e30f, mx1 = -1e30f;
        #pragma unroll
        for (int na = 0; na < 16; na++) {
            mx0 = fmaxf(mx0, fmaxf(sacc[na][0], sacc[na][1]));
            mx1 = fmaxf(mx1, fmaxf(sacc[na][2], sacc[na][3]));
        }
        mx0 = fmaxf(mx0, __shfl_xor_sync(0xffffffffu, mx0, 1));
        mx0 = fmaxf(mx0, __shfl_xor_sync(0xffffffffu, mx0, 2));
        mx1 = fmaxf(mx1, __shfl_xor_sync(0xffffffffu, mx1, 1));
        mx1 = fmaxf(mx1, __shfl_xor_sync(0xffffffffu, mx1, 2));
        float nm0 = fmaxf(m0, mx0), nm1 = fmaxf(m1, mx1);
        float a0 = expf(m0 - nm0), a1 = expf(m1 - nm1);
        float rs0 = 0.f, rs1 = 0.f;
        #pragma unroll
        for (int na = 0; na < 16; na++) {
            float p00 = expf(sacc[na][0] - nm0);
            float p01 = expf(sacc[na][1] - nm0);
            float p10 = expf(sacc[na][2] - nm1);
            float p11 = expf(sacc[na][3] - nm1);
            rs0 += p00 + p01; rs1 += p10 + p11;
            int col = na * 8 + tg * 2;
            *(float2*)(Ps + prow0 + col) = make_float2(p00, p01);
            *(float2*)(Ps + prow1 + col) = make_float2(p10, p11);
        }
        rs0 += __shfl_xor_sync(0xffffffffu, rs0, 1);
        rs0 += __shfl_xor_sync(0xffffffffu, rs0, 2);
        rs1 += __shfl_xor_sync(0xffffffffu, rs1, 1);
        rs1 += __shfl_xor_sync(0xffffffffu, rs1, 2);
        l0 = l0 * a0 + rs0; l1 = l1 * a1 + rs1;
        m0 = nm0; m1 = nm1;
        #pragma unroll
        for (int na2 = 0; na2 < 8; na2++) {
            oacc[na2][0] *= a0; oacc[na2][1] *= a0;
            oacc[na2][2] *= a1; oacc[na2][3] *= a1;
        }
        __syncthreads();                    // all warps' P writes visible

        // ---- O += P V ----
        const float* Vt = (const float*)(Vs + (j & 1) * FVSZ);
        #pragma unroll
        for (int kk = 0; kk < 16; kk++) {
            uint32_t pf[4];
            pf[0] = f2tf(Ps[prow0 + kk * 8 + tg]);
            pf[1] = f2tf(Ps[prow1 + kk * 8 + tg]);
            pf[2] = f2tf(Ps[prow0 + kk * 8 + tg + 4]);
            pf[3] = f2tf(Ps[prow1 + kk * 8 + tg + 4]);
            #pragma unroll
            for (int na2 = 0; na2 < 8; na2++) {
                uint32_t bf[2];
                bf[0] = __float_as_uint(Vt[(kk * 8 + tg) * VST + na2 * 8 + g]);
                bf[1] = __float_as_uint(Vt[(kk * 8 + tg + 4) * VST + na2 * 8 + g]);
                mma_tf32(oacc[na2], pf, bf);
            }
        }
    }

    // ---- epilogue: O / l -> gmem, tf32-rounded (feeds Wo GEMM A) ----
    float inv0 = 1.f / l0, inv1 = 1.f / l1;
    int r0 = qt * 128 + w * 16 + g;
    float* ob0 = o + (size_t)(bb * SS + r0) * EE + hh * DH;
    float* ob1 = ob0 + (size_t)8 * EE;
    #pragma unroll
    for (int na2 = 0; na2 < 8; na2++) {
        int col = na2 * 8 + tg * 2;
        *(float2*)(ob0 + col) = make_float2(roundtf(oacc[na2][0] * inv0),
                                            roundtf(oacc[na2][1] * inv0));
        *(float2*)(ob1 + col) = make_float2(roundtf(oacc[na2][2] * inv1),
                                            roundtf(oacc[na2][3] * inv1));
    }
}

// =====================================================================
// LayerNorm over last dim (512). Output tf32-rounded (feeds GEMM A).
// =====================================================================
__global__ void ln_kernel(const float* __restrict__ x, const float* __restrict__ g,
                          const float* __restrict__ b, float* __restrict__ y)
{
    long long row = blockIdx.x;
    const float* xr = x + row * EE;
    int tid = threadIdx.x;
    float4 v = *(const float4*)(xr + tid * 4);
    float s  = v.x + v.y + v.z + v.w;
    float s2 = v.x * v.x + v.y * v.y + v.z * v.z + v.w * v.w;
    #pragma unroll
    for (int o = 16; o > 0; o >>= 1) {
        s  += __shfl_xor_sync(0xffffffffu, s, o);
        s2 += __shfl_xor_sync(0xffffffffu, s2, o);
    }
    __shared__ float ss[4], ssq[4];
    int w = tid >> 5, l = tid & 31;
    if (l == 0) { ss[w] = s; ssq[w] = s2; }
    __syncthreads();
    s  = ss[0] + ss[1] + ss[2] + ss[3];
    s2 = ssq[0] + ssq[1] + ssq[2] + ssq[3];
    float m   = s * (1.0f / EE);
    float var = s2 * (1.0f / EE) - m * m;
    float inv = rsqrtf(var + 1e-5f);
    float4 gg = *(const float4*)(g + tid * 4);
    float4 bb = *(const float4*)(b + tid * 4);
    float4 o4;
    o4.x = roundtf((v.x - m) * inv * gg.x + bb.x);
    o4.y = roundtf((v.y - m) * inv * gg.y + bb.y);
    o4.z = roundtf((v.z - m) * inv * gg.z + bb.z);
    o4.w = roundtf((v.w - m) * inv * gg.w + bb.w);
    *(float4*)(y + row * EE + tid * 4) = o4;
}

// =====================================================================
// Mamba-style recurrence (R7 version, 4-way split accumulators).
// Uses ORIGINAL f32 Wi2h (not the rounded copy).
// =====================================================================
__global__ void __cluster_dims__(8, 1, 1) __launch_bounds__(256, 1)
recur_kernel(const float* __restrict__ XP, const float* __restrict__ h0,
             const float* __restrict__ Wi2h, float* __restrict__ hout)
{
    __shared__ float hbuf[2 * EE];
    __shared__ float partial[256];

    const int tid = threadIdx.x;
    const int b = blockIdx.x >> 3;
    const int r = blockIdx.x & 7;
    const int part = tid >> 6;
    const int e    = tid & 63;

    float4 w[32];
    {
        const float* wsrc = Wi2h + (long long)(r * 64 + e) * (2 * EE) + EE + part * 128;
        #pragma unroll
        for (int i = 0; i < 32; i++) w[i] = *(const float4*)(wsrc + i * 4);
    }
    if (tid < 128) *(float4*)(hbuf + tid * 4) = *(const float4*)(h0 + b * EE + tid * 4);

    uint32_t hb = (uint32_t)__cvta_generic_to_shared(hbuf);
    __syncthreads();
    asm volatile("barrier.cluster.arrive.aligned;" ::: "memory");
    asm volatile("barrier.cluster.wait.aligned;"   ::: "memory");

    const long long xpbase = (long long)b * SS * EE + r * 64 + e;

    for (int t = 0; t < SS; t++) {
        float xpv = 0.f;
        if (tid < 64) xpv = __ldg(XP + xpbase + (long long)t * EE);

        const float* hr = hbuf + (t & 1) * EE + part * 128;
        float a0 = 0.f, a1 = 0.f, a2 = 0.f, a3 = 0.f;
        #pragma unroll
        for (int i = 0; i < 32; i++) {
            float4 h4 = *(const float4*)(hr + i * 4);
            a0 += w[i].x * h4.x; a1 += w[i].y * h4.y;
            a2 += w[i].z * h4.z; a3 += w[i].w * h4.w;
        }
        partial[part * 64 + e] = (a0 + a1) + (a2 + a3);
        __syncthreads();

        if (tid < 64) {
            float sm = partial[e] + partial[64 + e] + partial[128 + e] + partial[192 + e] + xpv;
            float hn = tanhf(sm);
            hn = (hn > 0.f) ? hn : 0.f;
            uint32_t loff = hb + (uint32_t)((((t + 1) & 1) * EE + r * 64 + e) * 4);
            #pragma unroll
            for (int c = 0; c < 8; c++) {
                uint32_t ra;
                asm("mapa.shared::cluster.u32 %0, %1, %2;" : "=r"(ra) : "r"(loff), "r"(c));
                asm volatile("st.shared::cluster.f32 [%0], %1;" :: "r"(ra), "f"(hn));
            }
        }
        asm volatile("barrier.cluster.arrive.aligned;" ::: "memory");
        asm volatile("barrier.cluster.wait.aligned;"   ::: "memory");
    }
    if (tid < 64) hout[b * EE + r * 64 + e] = hbuf[r * 64 + e];
}

// =====================================================================
// Head (unchanged).
// =====================================================================
__global__ void head_kernel(const float* __restrict__ hfin, const float* __restrict__ Wh2o,
                            const float* __restrict__ bh2o, const float* __restrict__ Wc,
                            const float* __restrict__ bc, float* __restrict__ out, int half)
{
    int b = blockIdx.x, tid = threadIdx.x;
    __shared__ float hrow[EE];
    __shared__ float red[EE];
    hrow[tid] = hfin[b * EE + tid];
    __syncthreads();
    const float* wr = Wh2o + (long long)tid * EE;
    float acc = bh2o[tid];
    #pragma unroll 8
    for (int f = 0; f < EE; f += 4) {
        float4 w4 = *(const float4*)(wr + f);
        acc += w4.x * hrow[f] + w4.y * hrow[f + 1] + w4.z * hrow[f + 2] + w4.w * hrow[f + 3];
    }
    red[tid] = acc * Wc[tid];
    __syncthreads();
    for (int s = 256; s > 0; s >>= 1) {
        if (tid < s) red[tid] += red[tid + s];
        __syncthreads();
    }
    if (tid == 0) {
        float lg = red[0] + bc[0];
        out[b] = lg;
        out[half + b] = 1.f / (1.f + expf(-lg));
    }
}

// ---------------- host-side launch helpers ----------------
static const int GEMM_SMEM = 3 * (128 * 32 * 4 + 128 * 32 * 4);  // 98304

template<int EPI, bool CVTA, bool RND>
static void run_mm(const float* A, const float* B, const float* bias, float* C,
                   int M, int N, int K, int lda, int ldb, int ldc)
{
    cudaFuncSetAttribute(gemm_mma<EPI, CVTA, RND>,
                         cudaFuncAttributeMaxDynamicSharedMemorySize, GEMM_SMEM);
    dim3 grid(N / 128, M / 128, 1);
    gemm_mma<EPI, CVTA, RND><<<grid, 256, GEMM_SMEM>>>(A, B, bias, C, M, N, K, lda, ldb, ldc);
}

static void run_round(const float* src, float* dst, int n)
{
    round_kernel<<<(n + 255) / 256, 256>>>(src, dst, n);
}

extern "C" void kernel_launch(void* const* d_in, const int* in_sizes, int n_in,
                              void* d_out, int out_size)
{
    const float* bm   = (const float*)d_in[0];
    const float* h0   = (const float*)d_in[1];
    const float* Wp   = (const float*)d_in[2];
    const float* bp   = (const float*)d_in[3];
    const float* ln1g = (const float*)d_in[4];
    const float* ln1b = (const float*)d_in[5];
    const float* Wqkv = (const float*)d_in[6];
    const float* bqkv = (const float*)d_in[7];
    const float* Wo   = (const float*)d_in[8];
    const float* bo   = (const float*)d_in[9];
    const float* ln2g = (const float*)d_in[10];
    const float* ln2b = (const float*)d_in[11];
    const float* W1   = (const float*)d_in[12];
    const float* b1   = (const float*)d_in[13];
    const float* W2   = (const float*)d_in[14];
    const float* b2   = (const float*)d_in[15];
    const float* Wi2h = (const float*)d_in[16];
    const float* bi2h = (const float*)d_in[17];
    const float* Wh2o = (const float*)d_in[18];
    const float* bh2o = (const float*)d_in[19];
    const float* Wc   = (const float*)d_in[20];
    const float* bc   = (const float*)d_in[21];
    float* out = (float*)d_out;

    float *px, *pa, *pq, *po, *pf, *pxp, *ph, *pw;
    cudaGetSymbolAddress((void**)&px,  g_x);
    cudaGetSymbolAddress((void**)&pa,  g_a);
    cudaGetSymbolAddress((void**)&pq,  g_qkv);
    cudaGetSymbolAddress((void**)&po,  g_o);
    cudaGetSymbolAddress((void**)&pf,  g_f);
    cudaGetSymbolAddress((void**)&pxp, g_xp);
    cudaGetSymbolAddress((void**)&ph,  g_h);
    cudaGetSymbolAddress((void**)&pw,  g_wr);

    cudaFuncSetAttribute(flash_kernel,
                         cudaFuncAttributeMaxDynamicSharedMemorySize, FL_SMEM);

    // 0) pre-round all weights to tf32 bit patterns
    run_round(Wp,   pw + OFF_WP,   EE * DIN);
    run_round(Wqkv, pw + OFF_WQKV, LL * 3 * EE * EE);
    run_round(Wo,   pw + OFF_WO,   LL * EE * EE);
    run_round(W1,   pw + OFF_W1,   LL * FF * EE);
    run_round(W2,   pw + OFF_W2,   LL * EE * FF);
    run_round(Wi2h, pw + OFF_WI,   EE * 2 * EE);

    // 1) modality projection: x = bm @ Wp^T + bp   (A raw -> CVTA, out=residual -> no RND)
    run_mm<0, true, false>(bm, pw + OFF_WP, bp, px, MTOK, EE, DIN, DIN, DIN, EE);

    for (int l = 0; l < LL; l++) {
        const float* wqkv = pw + OFF_WQKV + (size_t)l * 3 * EE * EE;
        const float* bqk  = bqkv + (size_t)l * 3 * EE;
        const float* wo   = pw + OFF_WO + (size_t)l * EE * EE;
        const float* bo_  = bo   + (size_t)l * EE;
        const float* w1   = pw + OFF_W1 + (size_t)l * FF * EE;
        const float* b1_  = b1   + (size_t)l * FF;
        const float* w2   = pw + OFF_W2 + (size_t)l * EE * FF;
        const float* b2_  = b2   + (size_t)l * EE;

        // pre-LN attention (LN output rounded)
        ln_kernel<<<MTOK, 128>>>(px, ln1g + l * EE, ln1b + l * EE, pa);
        // QKV: A pre-rounded, output rounded (feeds flash)
        run_mm<0, false, true>(pa, wqkv, bqk, pq, MTOK, 3 * EE, EE, EE, EE, 3 * EE);

        // fused flash attention: qkv -> o (output rounded; feeds Wo GEMM)
        {
            dim3 grid(SS / 128, BB * HH);
            flash_kernel<<<grid, 256, FL_SMEM>>>(pq, po);
        }

        // x += O @ Wo^T + bo (A pre-rounded, residual out -> no RND)
        run_mm<2, false, false>(po, wo, bo_, px, MTOK, EE, EE, EE, EE, EE);

        // pre-LN FFN
        ln_kernel<<<MTOK, 128>>>(px, ln2g + l * EE, ln2b + l * EE, pa);
        // FFN1: A pre-rounded, gelu out rounded (feeds FFN2)
        run_mm<1, false, true>(pa, w1, b1_, pf, MTOK, FF, EE, EE, EE, FF);
        // FFN2: A pre-rounded, residual out -> no RND
        run_mm<2, false, false>(pf, w2, b2_, px, MTOK, EE, FF, FF, FF, EE);
    }

    // recurrence x-part: xp = x @ Wi2h[:, :E]^T + bi2h (A=x raw -> CVTA; out f32)
    run_mm<0, true, false>(px, pw + OFF_WI, bi2h, pxp, MTOK, EE, EE, EE, 2 * EE, EE);

    // sequential recurrence (persistent, clustered; original f32 Wi2h)
    recur_kernel<<<128, 256>>>(pxp, h0, Wi2h, ph);

    // head: logits + sigmoid
    head_kernel<<<BB, 512>>>(ph, Wh2o, bh2o, Wc, bc, out, out_size / 2);
}